// round 2
// baseline (speedup 1.0000x reference)
#include <cuda_runtime.h>

#define NNi   1024
#define BBi   8
#define TTi   40
#define DINi  16
#define ROWSi 8192
#define DT_SUB 0.025f

// ------------------- static scratch (no runtime allocation) -------------------
__device__ float g_A2 [(size_t)BBi*NNi*NNi];
__device__ float g_X  [(size_t)BBi*TTi*NNi*DINi];
__device__ float g_obs[(size_t)BBi*TTi*NNi];
__device__ float g_AX1[(size_t)BBi*TTi*NNi*DINi];
__device__ float g_AX2[(size_t)BBi*TTi*NNi*DINi];
__device__ float g_S  [(size_t)ROWSi*128];
__device__ float g_B1 [(size_t)ROWSi*128];
__device__ float g_B2 [(size_t)ROWSi*128];
__device__ float g_RH [(size_t)ROWSi*128];
__device__ float g_u  [(size_t)ROWSi*128];
__device__ float g_F  [(size_t)2*ROWSi*240];
__device__ float g_H1 [(size_t)2*ROWSi*64];
__device__ float g_pre[(size_t)TTi*ROWSi*128];
__device__ float g_T1 [(size_t)39*ROWSi*64];
__device__ float g_T2 [(size_t)39*ROWSi*64];

// ------------------- init kernels -------------------
__global__ void initX_k(const float4* __restrict__ v, const float4* __restrict__ m) {
    int i = blockIdx.x * 256 + threadIdx.x;   // [0, 327680)
    float s = 0.f;
#pragma unroll
    for (int q = 0; q < 4; q++) {
        float4 vv = v[i * 4 + q], mm = m[i * 4 + q];
        s += fabsf(mm.x) + fabsf(mm.y) + fabsf(mm.z) + fabsf(mm.w);
        float4 x = make_float4(vv.x * mm.x, vv.y * mm.y, vv.z * mm.z, vv.w * mm.w);
        ((float4*)g_X)[i * 4 + q] = x;
    }
    g_obs[i] = (s > 1e-4f) ? 1.f : 0.f;
}

__global__ void initS_k(const float* __restrict__ h0, const float* __restrict__ z0) {
    int i = blockIdx.x * 256 + threadIdx.x;   // [0, ROWSi*128)
    int c = i & 127;
    g_S[i] = (c < 64) ? h0[c] : z0[c - 64];
}

// ------------------- batched A-GEMM (both diffusion hops in one launch) -------------------
// Out[hop][b] = (hop ? Aop2 : Aop1)[b] @ B[b] ; tiles 128x128x16, 256 thr, 8x8/thread.
// bmode 0: B element = Bb[k*ldb + col] ; bmode 1: X layout, col -> (t=col>>4, ci=col&15)
// omode 0: Ob[row*ldo + col] ; omode 1: X layout
__global__ __launch_bounds__(256, 2) void gemmA_k(
    const float* __restrict__ Aop1, const float* __restrict__ Aop2,
    const float* __restrict__ Bsrc, size_t sB, int ldb, int bmode, int C,
    float* __restrict__ O1, float* __restrict__ O2, size_t sO, int ldo, int omode)
{
    int bz = blockIdx.z;
    int b = bz & 7, hop = bz >> 3;
    const float* Ab = (hop ? Aop2 : Aop1) + (size_t)b * NNi * NNi;
    const float* Bb = Bsrc + (size_t)b * sB;
    float* Ob = (hop ? O2 : O1) + (size_t)b * sO;
    int row0 = blockIdx.x * 128, col0 = blockIdx.y * 128;

    __shared__ float As[16][128];
    __shared__ float Bs[16][128];

    int t  = threadIdx.x;
    int tx = t & 15, ty = t >> 4;
    int rA = ty * 4, cB = tx * 4;

    float acc[2][2][4][4];
#pragma unroll
    for (int a = 0; a < 2; a++)
#pragma unroll
        for (int c = 0; c < 2; c++)
#pragma unroll
            for (int i = 0; i < 4; i++)
#pragma unroll
                for (int j = 0; j < 4; j++) acc[a][c][i][j] = 0.f;

    for (int k0 = 0; k0 < NNi; k0 += 16) {
#pragma unroll
        for (int i = 0; i < 2; i++) {              // A tile 128 rows x 16 k
            int f = t + i * 256;
            int row = f >> 2, kq = (f & 3) * 4;
            float4 v = *(const float4*)&Ab[(size_t)(row0 + row) * NNi + k0 + kq];
            As[kq + 0][row] = v.x; As[kq + 1][row] = v.y;
            As[kq + 2][row] = v.z; As[kq + 3][row] = v.w;
        }
#pragma unroll
        for (int i = 0; i < 2; i++) {              // B tile 16 k x 128 cols
            int f = t + i * 256;
            int k = f >> 5, cq = (f & 31) * 4;
            int col = col0 + cq;
            size_t off;
            if (bmode == 1) off = (size_t)(k0 + k) * 16 + (size_t)(col >> 4) * 16384 + (col & 15);
            else            off = (size_t)(k0 + k) * ldb + col;
            *(float4*)&Bs[k][cq] = *(const float4*)&Bb[off];
        }
        __syncthreads();
#pragma unroll
        for (int k = 0; k < 16; k++) {
            float a[2][4], bb[2][4];
            *(float4*)a[0]  = *(const float4*)&As[k][rA];
            *(float4*)a[1]  = *(const float4*)&As[k][rA + 64];
            *(float4*)bb[0] = *(const float4*)&Bs[k][cB];
            *(float4*)bb[1] = *(const float4*)&Bs[k][cB + 64];
#pragma unroll
            for (int rh = 0; rh < 2; rh++)
#pragma unroll
                for (int ch = 0; ch < 2; ch++)
#pragma unroll
                    for (int i = 0; i < 4; i++)
#pragma unroll
                        for (int j = 0; j < 4; j++)
                            acc[rh][ch][i][j] += a[rh][i] * bb[ch][j];
        }
        __syncthreads();
    }
#pragma unroll
    for (int rh = 0; rh < 2; rh++)
#pragma unroll
        for (int i = 0; i < 4; i++) {
            int row = row0 + rA + rh * 64 + i;
#pragma unroll
            for (int ch = 0; ch < 2; ch++) {
                int col = col0 + cB + ch * 64;
                size_t off;
                if (omode == 1) off = (size_t)row * 16 + (size_t)(col >> 4) * 16384 + (col & 15);
                else            off = (size_t)row * ldo + col;
                *(float4*)&Ob[off] = *(float4*)&acc[rh][ch][i][0];
            }
        }
}

// ------------------- feature gathers -------------------
__global__ void gatherODE_k() {   // F[cell][row][192] = [h, Ah, A2h]
    int idx = blockIdx.x * 256 + threadIdx.x;           // [0, 2*8192*48)
    int cell = idx / 393216;
    int rem = idx - cell * 393216;
    int row = rem / 48;
    int c = (rem - row * 48) * 4;
    const float* src = (c < 64) ? g_S : ((c < 128) ? g_B1 : g_B2);
    float4 v = *(const float4*)&src[(size_t)row * 128 + cell * 64 + (c & 63)];
    *(float4*)&g_F[((size_t)cell * ROWSi + row) * 192 + c] = v;
}

__global__ void gatherGRU_k(const float* __restrict__ Hsrc, int t) { // K=240
    int idx = blockIdx.x * 256 + threadIdx.x;           // [0, 2*8192*60)
    int cell = idx / 491520;
    int rem = idx - cell * 491520;
    int row = rem / 60;
    int c = (rem - row * 60) * 4;
    int b = row >> 10, n = row & 1023;
    size_t xbase = (((size_t)b * TTi + t) * NNi + n) * 16;
    float4 v;
    if (c < 16)        v = *(const float4*)&g_X  [xbase + c];
    else if (c < 80)   v = *(const float4*)&Hsrc [(size_t)row * 128 + cell * 64 + (c - 16)];
    else if (c < 96)   v = *(const float4*)&g_AX1[xbase + (c - 80)];
    else if (c < 160)  v = *(const float4*)&g_B1 [(size_t)row * 128 + cell * 64 + (c - 96)];
    else if (c < 176)  v = *(const float4*)&g_AX2[xbase + (c - 160)];
    else               v = *(const float4*)&g_B2 [(size_t)row * 128 + cell * 64 + (c - 176)];
    *(float4*)&g_F[((size_t)cell * ROWSi + row) * 240 + c] = v;
}

// ------------------- generic small GEMM with fused epilogues -------------------
// Out = epilogue(A @ W + bias). Tiles 128x64x16, 256 thr, 8x4/thread. z selects cell.
// modes: 0 tanh->Out | 1 Euler: S += dt*tanh, opt write pre[t] | 2 gate: r*h->g_RH, u->g_u
//        3 cand: GRU blend into S | 4 sigmoid*hpre -> Out | 5 plain -> d_out (remapped)
__global__ __launch_bounds__(256, 2) void dense_k(
    const float* __restrict__ Ain, int lda, size_t aB,
    const float* __restrict__ W0, const float* __restrict__ W1,
    const float* __restrict__ bias0, const float* __restrict__ bias1,
    int Kdim, int Nout, int mode, int t,
    float* __restrict__ Out, int ldo, size_t oB)
{
    int z = blockIdx.z;
    const float* Ab = Ain + (size_t)z * aB;
    const float* W = z ? W1 : W0;
    const float* bias = z ? bias1 : bias0;
    int row0 = blockIdx.x * 128, col0 = blockIdx.y * 64;

    __shared__ float As[16][128];
    __shared__ float Bs[16][64];

    int tt = threadIdx.x;
    int tx = tt & 15, ty = tt >> 4;
    int rA = ty * 4, cBl = tx * 4;

    float acc[2][4][4];
#pragma unroll
    for (int a = 0; a < 2; a++)
#pragma unroll
        for (int i = 0; i < 4; i++)
#pragma unroll
            for (int j = 0; j < 4; j++) acc[a][i][j] = 0.f;

    for (int k0 = 0; k0 < Kdim; k0 += 16) {
#pragma unroll
        for (int i = 0; i < 2; i++) {
            int f = tt + i * 256;
            int row = f >> 2, kq = (f & 3) * 4;
            float4 v = *(const float4*)&Ab[(size_t)(row0 + row) * lda + k0 + kq];
            As[kq + 0][row] = v.x; As[kq + 1][row] = v.y;
            As[kq + 2][row] = v.z; As[kq + 3][row] = v.w;
        }
        {
            int k = tt >> 4, cq = (tt & 15) * 4;
            int col = col0 + cq;
            float4 v = make_float4(0.f, 0.f, 0.f, 0.f);
            if (col < Nout) v = *(const float4*)&W[(size_t)(k0 + k) * Nout + col];
            *(float4*)&Bs[k][cq] = v;
        }
        __syncthreads();
#pragma unroll
        for (int k = 0; k < 16; k++) {
            float a0[4], a1[4], bv[4];
            *(float4*)a0 = *(const float4*)&As[k][rA];
            *(float4*)a1 = *(const float4*)&As[k][rA + 64];
            *(float4*)bv = *(const float4*)&Bs[k][cBl];
#pragma unroll
            for (int i = 0; i < 4; i++)
#pragma unroll
                for (int j = 0; j < 4; j++) {
                    acc[0][i][j] += a0[i] * bv[j];
                    acc[1][i][j] += a1[i] * bv[j];
                }
        }
        __syncthreads();
    }

#pragma unroll
    for (int rh = 0; rh < 2; rh++)
#pragma unroll
        for (int i = 0; i < 4; i++) {
            int row = row0 + rA + rh * 64 + i;
#pragma unroll
            for (int j = 0; j < 4; j++) {
                int col = col0 + cBl + j;
                if (col >= Nout) continue;
                float v = acc[rh][i][j] + bias[col];
                if (mode == 0) {
                    Out[(size_t)z * oB + (size_t)row * ldo + col] = tanhf(v);
                } else if (mode == 1) {
                    size_t ii = (size_t)row * 128 + z * 64 + col;
                    float s = g_S[ii] + DT_SUB * tanhf(v);
                    g_S[ii] = s;
                    if (t >= 0) g_pre[(size_t)t * ((size_t)ROWSi * 128) + ii] = s;
                } else if (mode == 2) {
                    float g = 1.f / (1.f + expf(-v));
                    if (col < 64) {
                        size_t ii = (size_t)row * 128 + z * 64 + col;
                        g_RH[ii] = g * g_S[ii];
                    } else {
                        g_u[(size_t)row * 128 + z * 64 + (col - 64)] = g;
                    }
                } else if (mode == 3) {
                    float cc = tanhf(v);
                    size_t ii = (size_t)row * 128 + z * 64 + col;
                    float u = g_u[ii], h = g_S[ii];
                    float m = g_obs[((size_t)(row >> 10) * TTi + t) * NNi + (row & 1023)];
                    float hn = u * h + (1.f - u) * cc;
                    g_S[ii] = h + m * (hn - h);
                } else if (mode == 4) {
                    float g = 1.f / (1.f + expf(-v));
                    Out[(size_t)row * 64 + col] =
                        g * g_pre[(size_t)ROWSi * 128 + (size_t)row * 128 + col];
                } else { // 5: final output, remap t-major -> b-major [8,39,1024,16]
                    int tp = row >> 13, bn = row & 8191;
                    int bb = bn >> 10, n = bn & 1023;
                    Out[(((size_t)bb * 39 + tp) * NNi + n) * 16 + col] = v;
                }
            }
        }
}

// ------------------- host orchestration -------------------
extern "C" void kernel_launch(void* const* d_in, const int* in_sizes, int n_in,
                              void* d_out, int out_size) {
    const float* values  = (const float*)d_in[0];
    const float* masks   = (const float*)d_in[1];
    const float* A       = (const float*)d_in[2];
    const float* h0      = (const float*)d_in[3];
    const float* z0      = (const float*)d_in[4];
    const float* gV_Wg   = (const float*)d_in[5];
    const float* gV_bg   = (const float*)d_in[6];
    const float* gV_Wc   = (const float*)d_in[7];
    const float* gV_bc   = (const float*)d_in[8];
    const float* gG_Wg   = (const float*)d_in[9];
    const float* gG_bg   = (const float*)d_in[10];
    const float* gG_Wc   = (const float*)d_in[11];
    const float* gG_bc   = (const float*)d_in[12];
    const float* oV_W0   = (const float*)d_in[13];
    const float* oV_b0   = (const float*)d_in[14];
    const float* oV_Wout = (const float*)d_in[15];
    const float* oV_bout = (const float*)d_in[16];
    const float* oG_W0   = (const float*)d_in[17];
    const float* oG_b0   = (const float*)d_in[18];
    const float* oG_Wout = (const float*)d_in[19];
    const float* oG_bout = (const float*)d_in[20];
    const float* Wz1     = (const float*)d_in[21];
    const float* bz1     = (const float*)d_in[22];
    const float* Wz2     = (const float*)d_in[23];
    const float* bz2     = (const float*)d_in[24];
    const float* Wz3     = (const float*)d_in[25];
    const float* bz3     = (const float*)d_in[26];
    const float* Wo      = (const float*)d_in[27];
    const float* bo      = (const float*)d_in[28];

    float *pA2, *pX, *pAX1, *pAX2, *pS, *pB1, *pB2, *pRH, *pF, *pH1, *pT1, *pT2, *pPre;
    cudaGetSymbolAddress((void**)&pA2,  g_A2);
    cudaGetSymbolAddress((void**)&pX,   g_X);
    cudaGetSymbolAddress((void**)&pAX1, g_AX1);
    cudaGetSymbolAddress((void**)&pAX2, g_AX2);
    cudaGetSymbolAddress((void**)&pS,   g_S);
    cudaGetSymbolAddress((void**)&pB1,  g_B1);
    cudaGetSymbolAddress((void**)&pB2,  g_B2);
    cudaGetSymbolAddress((void**)&pRH,  g_RH);
    cudaGetSymbolAddress((void**)&pF,   g_F);
    cudaGetSymbolAddress((void**)&pH1,  g_H1);
    cudaGetSymbolAddress((void**)&pT1,  g_T1);
    cudaGetSymbolAddress((void**)&pT2,  g_T2);
    cudaGetSymbolAddress((void**)&pPre, g_pre);

    const size_t sA = (size_t)NNi * NNi;          // per-batch A stride
    const size_t sX = (size_t)TTi * NNi * DINi;   // per-batch X stride
    const size_t sS = (size_t)NNi * 128;          // per-batch state stride

    initX_k<<<1280, 256>>>((const float4*)values, (const float4*)masks);
    initS_k<<<4096, 256>>>(h0, z0);

    // A2 = A @ A  (single hop: grid.z = 8)
    gemmA_k<<<dim3(8, 8, 8), 256>>>(A, A, A, sA, NNi, 0, 1024, pA2, pA2, sA, NNi, 0);
    // AX1 = A @ X, AX2 = A2 @ X for all 40 steps (640 cols)
    gemmA_k<<<dim3(8, 5, 16), 256>>>(A, pA2, pX, sX, 0, 1, 640, pAX1, pAX2, sX, 0, 1);

    for (int t = 0; t < TTi; t++) {
        for (int sub = 0; sub < 2; sub++) {       // Euler substeps
            gemmA_k<<<dim3(8, 1, 16), 256>>>(A, pA2, pS, sS, 128, 0, 128, pB1, pB2, sS, 128, 0);
            gatherODE_k<<<3072, 256>>>();
            dense_k<<<dim3(64, 1, 2), 256>>>(pF, 192, (size_t)ROWSi * 192,
                oV_W0, oG_W0, oV_b0, oG_b0, 192, 64, 0, -1, pH1, 64, (size_t)ROWSi * 64);
            dense_k<<<dim3(64, 1, 2), 256>>>(pH1, 64, (size_t)ROWSi * 64,
                oV_Wout, oG_Wout, oV_bout, oG_bout, 64, 64, 1, (sub == 1) ? t : -1, pS, 0, 0);
        }
        // GRU gate
        gemmA_k<<<dim3(8, 1, 16), 256>>>(A, pA2, pS, sS, 128, 0, 128, pB1, pB2, sS, 128, 0);
        gatherGRU_k<<<3840, 256>>>(pS, t);
        dense_k<<<dim3(64, 2, 2), 256>>>(pF, 240, (size_t)ROWSi * 240,
            gV_Wg, gG_Wg, gV_bg, gG_bg, 240, 128, 2, t, pS, 0, 0);
        // GRU candidate + blend
        gemmA_k<<<dim3(8, 1, 16), 256>>>(A, pA2, pRH, sS, 128, 0, 128, pB1, pB2, sS, 128, 0);
        gatherGRU_k<<<3840, 256>>>(pRH, t);
        dense_k<<<dim3(64, 1, 2), 256>>>(pF, 240, (size_t)ROWSi * 240,
            gV_Wc, gG_Wc, gV_bc, gG_bc, 240, 64, 3, t, pS, 0, 0);
    }

    // Output head over t = 1..39 (rows = 39*8192 = 319488 = 2496*128)
    dense_k<<<dim3(2496, 1, 1), 256>>>(pPre + (size_t)ROWSi * 128 + 64, 128, 0,
        Wz1, Wz1, bz1, bz1, 64, 64, 0, -1, pT1, 64, 0);
    dense_k<<<dim3(2496, 1, 1), 256>>>(pT1, 64, 0,
        Wz2, Wz2, bz2, bz2, 64, 64, 0, -1, pT2, 64, 0);
    dense_k<<<dim3(2496, 1, 1), 256>>>(pT2, 64, 0,
        Wz3, Wz3, bz3, bz3, 64, 64, 4, -1, pT1, 64, 0);
    dense_k<<<dim3(2496, 1, 1), 256>>>(pT1, 64, 0,
        Wo, Wo, bo, bo, 64, 16, 5, -1, (float*)d_out, 16, 0);
}

// round 4
// speedup vs baseline: 1.9016x; 1.9016x over previous
#include <cuda_runtime.h>
#include <cuda_bf16.h>
#include <cstdint>

#define NNi   1024
#define BBi   8
#define TTi   40
#define DINi  16
#define ROWSi 8192
#define DT_SUB 0.025f

typedef __nv_bfloat16 bf16;

// ------------------- static scratch (no runtime allocation) -------------------
__device__ float g_A2 [(size_t)BBi*NNi*NNi];
__device__ float g_X  [(size_t)BBi*TTi*NNi*DINi];
__device__ float g_obs[(size_t)BBi*TTi*NNi];
__device__ float g_AX1[(size_t)BBi*TTi*NNi*DINi];
__device__ float g_AX2[(size_t)BBi*TTi*NNi*DINi];
__device__ float g_S  [(size_t)ROWSi*128];
__device__ float g_B1 [(size_t)ROWSi*128];
__device__ float g_B2 [(size_t)ROWSi*128];
__device__ float g_RH [(size_t)ROWSi*128];
__device__ float g_u  [(size_t)ROWSi*128];
__device__ float g_H1 [(size_t)2*ROWSi*64];
__device__ float g_pre[(size_t)TTi*ROWSi*128];
__device__ float g_T1 [(size_t)39*ROWSi*64];
__device__ float g_T2 [(size_t)39*ROWSi*64];
// bf16 split operands
__device__ bf16 g_Ahi [(size_t)BBi*NNi*NNi];
__device__ bf16 g_Alo [(size_t)BBi*NNi*NNi];
__device__ bf16 g_A2hi[(size_t)BBi*NNi*NNi];
__device__ bf16 g_A2lo[(size_t)BBi*NNi*NNi];
__device__ bf16 g_Shi [(size_t)ROWSi*128];
__device__ bf16 g_Slo [(size_t)ROWSi*128];
__device__ bf16 g_RHhi[(size_t)ROWSi*128];
__device__ bf16 g_RHlo[(size_t)ROWSi*128];

// ------------------- small asm helpers (all plain sm_80+ features) -------------------
__device__ __forceinline__ uint32_t smem_u32(const void* p) {
    uint32_t a;
    asm("{ .reg .u64 t; cvta.to.shared.u64 t, %1; cvt.u32.u64 %0, t; }" : "=r"(a) : "l"(p));
    return a;
}
__device__ __forceinline__ void ldm4(uint32_t* r, uint32_t a) {
    asm volatile("ldmatrix.sync.aligned.m8n8.x4.shared.b16 {%0,%1,%2,%3}, [%4];"
        : "=r"(r[0]), "=r"(r[1]), "=r"(r[2]), "=r"(r[3]) : "r"(a));
}
__device__ __forceinline__ void ldm4t(uint32_t* r, uint32_t a) {
    asm volatile("ldmatrix.sync.aligned.m8n8.x4.trans.shared.b16 {%0,%1,%2,%3}, [%4];"
        : "=r"(r[0]), "=r"(r[1]), "=r"(r[2]), "=r"(r[3]) : "r"(a));
}
__device__ __forceinline__ void mma_bf(float* c, const uint32_t* a, uint32_t b0, uint32_t b1) {
    asm volatile("mma.sync.aligned.m16n8k16.row.col.f32.bf16.bf16.f32 "
        "{%0,%1,%2,%3}, {%4,%5,%6,%7}, {%8,%9}, {%0,%1,%2,%3};"
        : "+f"(c[0]), "+f"(c[1]), "+f"(c[2]), "+f"(c[3])
        : "r"(a[0]), "r"(a[1]), "r"(a[2]), "r"(a[3]), "r"(b0), "r"(b1));
}
__device__ __forceinline__ void cpa16(uint32_t sm, const void* gm) {
    asm volatile("cp.async.cg.shared.global [%0], [%1], 16;"
        :: "r"(sm), "l"(__cvta_generic_to_global(gm)));
}
#define CP_COMMIT() asm volatile("cp.async.commit_group;" ::: "memory")
#define CP_WAIT0()  asm volatile("cp.async.wait_group 0;" ::: "memory")
#define CP_WAIT1()  asm volatile("cp.async.wait_group 1;" ::: "memory")

__device__ __forceinline__ void split_bf(float v, bf16& h, bf16& l) {
    h = __float2bfloat16_rn(v);
    l = __float2bfloat16_rn(v - __bfloat162float(h));
}

// ------------------- init kernels -------------------
__global__ void initX_k(const float4* __restrict__ v, const float4* __restrict__ m) {
    int i = blockIdx.x * 256 + threadIdx.x;
    float s = 0.f;
#pragma unroll
    for (int q = 0; q < 4; q++) {
        float4 vv = v[i * 4 + q], mm = m[i * 4 + q];
        s += fabsf(mm.x) + fabsf(mm.y) + fabsf(mm.z) + fabsf(mm.w);
        float4 x = make_float4(vv.x * mm.x, vv.y * mm.y, vv.z * mm.z, vv.w * mm.w);
        ((float4*)g_X)[i * 4 + q] = x;
    }
    g_obs[i] = (s > 1e-4f) ? 1.f : 0.f;
}
__global__ void initS_k(const float* __restrict__ h0, const float* __restrict__ z0) {
    int i = blockIdx.x * 256 + threadIdx.x;
    int c = i & 127;
    float v = (c < 64) ? h0[c] : z0[c - 64];
    g_S[i] = v;
    split_bf(v, g_Shi[i], g_Slo[i]);
}
__global__ void splitA_k(const float* __restrict__ src, bf16* __restrict__ hi, bf16* __restrict__ lo) {
    size_t i = (size_t)blockIdx.x * 256 + threadIdx.x;   // grid covers 8M
    split_bf(src[i], hi[i], lo[i]);
}

// ------------------- HMMA bf16 3-pass diffusion GEMM -------------------
// O[hop][b][1024][128] = (hop ? A2 : A)[b] @ State[b]  (A pre-split bf16, State pre-split bf16)
// grid (8, 1, 16), 256 thr (8 warps, 4x2), CTA tile 128x128, ktile 32, cp.async double buffer.
// smem per stage: Ahi[128][40]b16 Alo | Bhi[32][136]b16 Blo  = 37888 B
#define STAGE_BYTES 37888
#define A_LO_OFF    10240
#define B_OFF       20480
#define B_LO_OFF    8704

__device__ __forceinline__ void hmma_load_stage(
    uint32_t so, int k0, int t, int row0,
    const bf16* __restrict__ Ah, const bf16* __restrict__ Al,
    const bf16* __restrict__ Bh, const bf16* __restrict__ Bl)
{
#pragma unroll
    for (int i = 0; i < 4; i++) {             // A: 1024 chunks (hi 512 + lo 512)
        int c = t + i * 256;
        int arr = c >> 9, cc = c & 511, row = cc >> 2, seg = cc & 3;
        const bf16* g = (arr ? Al : Ah) + (size_t)(row0 + row) * NNi + k0 + seg * 8;
        cpa16(so + arr * A_LO_OFF + row * 80 + seg * 16, g);
    }
#pragma unroll
    for (int i = 0; i < 4; i++) {             // B: 1024 chunks
        int c = t + i * 256;
        int arr = c >> 9, cc = c & 511, k = cc >> 4, seg = cc & 15;
        const bf16* g = (arr ? Bl : Bh) + (size_t)(k0 + k) * 128 + seg * 8;
        cpa16(so + B_OFF + arr * B_LO_OFF + k * 272 + seg * 16, g);
    }
    CP_COMMIT();
}

__global__ void __launch_bounds__(256, 2) gemmA_hmma(
    const bf16* __restrict__ Ahi1, const bf16* __restrict__ Alo1,
    const bf16* __restrict__ Ahi2, const bf16* __restrict__ Alo2,
    const bf16* __restrict__ Bhi, const bf16* __restrict__ Blo,
    float* __restrict__ O1, float* __restrict__ O2)
{
    extern __shared__ char smraw[];
    int bz = blockIdx.z;
    int b = bz & 7, hop = bz >> 3;
    const bf16* Ah = (hop ? Ahi2 : Ahi1) + (size_t)b * NNi * NNi;
    const bf16* Al = (hop ? Alo2 : Alo1) + (size_t)b * NNi * NNi;
    const bf16* Bh = Bhi + (size_t)b * NNi * 128;
    const bf16* Bl = Blo + (size_t)b * NNi * 128;
    float* Ob = (hop ? O2 : O1) + (size_t)b * NNi * 128;
    int row0 = blockIdx.x * 128;

    int t = threadIdx.x, wid = t >> 5, lane = t & 31;
    int wm = (wid & 3) * 32, wn = (wid >> 2) * 64;
    uint32_t sbase = smem_u32(smraw);

    float acc[2][8][4];
#pragma unroll
    for (int mt = 0; mt < 2; mt++)
#pragma unroll
        for (int nt = 0; nt < 8; nt++)
#pragma unroll
            for (int q = 0; q < 4; q++) acc[mt][nt][q] = 0.f;

    uint32_t lmRow  = lane & 15;
    uint32_t lmColB = (lane >> 4) * 16;

    hmma_load_stage(sbase, 0, t, row0, Ah, Al, Bh, Bl);

    for (int kt = 0; kt < 32; kt++) {
        if (kt < 31)
            hmma_load_stage(sbase + ((kt + 1) & 1) * STAGE_BYTES, (kt + 1) * 32, t, row0, Ah, Al, Bh, Bl);
        if (kt < 31) { CP_WAIT1(); } else { CP_WAIT0(); }
        __syncthreads();

        uint32_t so = sbase + (kt & 1) * STAGE_BYTES;
#pragma unroll
        for (int ks = 0; ks < 2; ks++) {
            uint32_t ah[2][4], al[2][4];
#pragma unroll
            for (int mt = 0; mt < 2; mt++) {
                uint32_t ad = so + (wm + mt * 16 + lmRow) * 80 + ks * 32 + lmColB;
                ldm4(ah[mt], ad);
                ldm4(al[mt], ad + A_LO_OFF);
            }
#pragma unroll
            for (int np = 0; np < 4; np++) {
                uint32_t bd = so + B_OFF + (ks * 16 + lmRow) * 272 + (wn + np * 16) * 2 + lmColB;
                uint32_t bh[4], bl[4];
                ldm4t(bh, bd);
                ldm4t(bl, bd + B_LO_OFF);
#pragma unroll
                for (int mt = 0; mt < 2; mt++) {
                    mma_bf(acc[mt][2 * np],     ah[mt], bh[0], bh[1]);
                    mma_bf(acc[mt][2 * np + 1], ah[mt], bh[2], bh[3]);
                    mma_bf(acc[mt][2 * np],     ah[mt], bl[0], bl[1]);
                    mma_bf(acc[mt][2 * np + 1], ah[mt], bl[2], bl[3]);
                    mma_bf(acc[mt][2 * np],     al[mt], bh[0], bh[1]);
                    mma_bf(acc[mt][2 * np + 1], al[mt], bh[2], bh[3]);
                }
            }
        }
        __syncthreads();
    }

    int gr = lane >> 2, gc = (lane & 3) * 2;
#pragma unroll
    for (int mt = 0; mt < 2; mt++)
#pragma unroll
        for (int nt = 0; nt < 8; nt++) {
            int r = row0 + wm + mt * 16 + gr;
            int c = wn + nt * 8 + gc;
            *(float2*)&Ob[(size_t)r * 128 + c]       = make_float2(acc[mt][nt][0], acc[mt][nt][1]);
            *(float2*)&Ob[(size_t)(r + 8) * 128 + c] = make_float2(acc[mt][nt][2], acc[mt][nt][3]);
        }
}

// ------------------- SIMT batched A-GEMM (precompute only) -------------------
__global__ __launch_bounds__(256, 2) void gemmA_k(
    const float* __restrict__ Aop1, const float* __restrict__ Aop2,
    const float* __restrict__ Bsrc, size_t sB, int ldb, int bmode, int C,
    float* __restrict__ O1, float* __restrict__ O2, size_t sO, int ldo, int omode)
{
    int bz = blockIdx.z;
    int b = bz & 7, hop = bz >> 3;
    const float* Ab = (hop ? Aop2 : Aop1) + (size_t)b * NNi * NNi;
    const float* Bb = Bsrc + (size_t)b * sB;
    float* Ob = (hop ? O2 : O1) + (size_t)b * sO;
    int row0 = blockIdx.x * 128, col0 = blockIdx.y * 128;

    __shared__ float As[16][128];
    __shared__ float Bs[16][128];

    int t  = threadIdx.x;
    int tx = t & 15, ty = t >> 4;
    int rA = ty * 4, cB = tx * 4;

    float acc[2][2][4][4];
#pragma unroll
    for (int a = 0; a < 2; a++)
#pragma unroll
        for (int c = 0; c < 2; c++)
#pragma unroll
            for (int i = 0; i < 4; i++)
#pragma unroll
                for (int j = 0; j < 4; j++) acc[a][c][i][j] = 0.f;

    for (int k0 = 0; k0 < NNi; k0 += 16) {
#pragma unroll
        for (int i = 0; i < 2; i++) {
            int f = t + i * 256;
            int row = f >> 2, kq = (f & 3) * 4;
            float4 v = *(const float4*)&Ab[(size_t)(row0 + row) * NNi + k0 + kq];
            As[kq + 0][row] = v.x; As[kq + 1][row] = v.y;
            As[kq + 2][row] = v.z; As[kq + 3][row] = v.w;
        }
#pragma unroll
        for (int i = 0; i < 2; i++) {
            int f = t + i * 256;
            int k = f >> 5, cq = (f & 31) * 4;
            int col = col0 + cq;
            size_t off;
            if (bmode == 1) off = (size_t)(k0 + k) * 16 + (size_t)(col >> 4) * 16384 + (col & 15);
            else            off = (size_t)(k0 + k) * ldb + col;
            *(float4*)&Bs[k][cq] = *(const float4*)&Bb[off];
        }
        __syncthreads();
#pragma unroll
        for (int k = 0; k < 16; k++) {
            float a[2][4], bb[2][4];
            *(float4*)a[0]  = *(const float4*)&As[k][rA];
            *(float4*)a[1]  = *(const float4*)&As[k][rA + 64];
            *(float4*)bb[0] = *(const float4*)&Bs[k][cB];
            *(float4*)bb[1] = *(const float4*)&Bs[k][cB + 64];
#pragma unroll
            for (int rh = 0; rh < 2; rh++)
#pragma unroll
                for (int ch = 0; ch < 2; ch++)
#pragma unroll
                    for (int i = 0; i < 4; i++)
#pragma unroll
                        for (int j = 0; j < 4; j++)
                            acc[rh][ch][i][j] += a[rh][i] * bb[ch][j];
        }
        __syncthreads();
    }
#pragma unroll
    for (int rh = 0; rh < 2; rh++)
#pragma unroll
        for (int i = 0; i < 4; i++) {
            int row = row0 + rA + rh * 64 + i;
#pragma unroll
            for (int ch = 0; ch < 2; ch++) {
                int col = col0 + cB + ch * 64;
                size_t off;
                if (omode == 1) off = (size_t)row * 16 + (size_t)(col >> 4) * 16384 + (col & 15);
                else            off = (size_t)row * ldo + col;
                *(float4*)&Ob[off] = *(float4*)&acc[rh][ch][i][0];
            }
        }
}

// ------------------- generic small GEMM with fused feature-gather + epilogues -------------------
// afmt 0: A from Ain[row][k] (lda). afmt 1: ODE feats [h|Ah|A2h] (K=192), cell=z.
// afmt 2: GRU feats [x|h|Ax|Ah|A2x|A2h] (K=240), h from Hsrc, cell=z, time t.
// modes: 0 tanh->Out | 1 Euler S += dt*tanh (+pre[t], +splits) | 2 gate r*h->RH(+splits), u
//        3 cand blend -> S (+splits) | 4 sigmoid*hpre -> Out | 5 plain -> d_out remapped
__global__ __launch_bounds__(256, 2) void dense_k(
    const float* __restrict__ Ain, int lda, size_t aB,
    const float* __restrict__ W0, const float* __restrict__ W1,
    const float* __restrict__ bias0, const float* __restrict__ bias1,
    int Kdim, int Nout, int mode, int t,
    float* __restrict__ Out, int ldo, size_t oB,
    int afmt, const float* __restrict__ Hsrc)
{
    int z = blockIdx.z;
    const float* Ab = Ain + (size_t)z * aB;
    const float* W = z ? W1 : W0;
    const float* bias = z ? bias1 : bias0;
    int row0 = blockIdx.x * 128, col0 = blockIdx.y * 64;

    __shared__ float As[16][128];
    __shared__ float Bs[16][64];

    int tt = threadIdx.x;
    int tx = tt & 15, ty = tt >> 4;
    int rA = ty * 4, cBl = tx * 4;

    float acc[2][4][4];
#pragma unroll
    for (int a = 0; a < 2; a++)
#pragma unroll
        for (int i = 0; i < 4; i++)
#pragma unroll
            for (int j = 0; j < 4; j++) acc[a][i][j] = 0.f;

    for (int k0 = 0; k0 < Kdim; k0 += 16) {
#pragma unroll
        for (int i = 0; i < 2; i++) {
            int f = tt + i * 256;
            int row = row0 + (f >> 2);
            int kk = k0 + (f & 3) * 4;
            float4 v;
            if (afmt == 0) {
                v = *(const float4*)&Ab[(size_t)(row) * lda + kk];
            } else if (afmt == 1) {
                const float* p; size_t off;
                if (kk < 64)       { p = g_S;  off = (size_t)row * 128 + z * 64 + kk; }
                else if (kk < 128) { p = g_B1; off = (size_t)row * 128 + z * 64 + (kk - 64); }
                else               { p = g_B2; off = (size_t)row * 128 + z * 64 + (kk - 128); }
                v = *(const float4*)&p[off];
            } else {
                int bb = row >> 10, n = row & 1023;
                size_t xb = (((size_t)bb * TTi + t) * NNi + n) * 16;
                const float* p; size_t off;
                if (kk < 16)       { p = g_X;   off = xb + kk; }
                else if (kk < 80)  { p = Hsrc;  off = (size_t)row * 128 + z * 64 + (kk - 16); }
                else if (kk < 96)  { p = g_AX1; off = xb + (kk - 80); }
                else if (kk < 160) { p = g_B1;  off = (size_t)row * 128 + z * 64 + (kk - 96); }
                else if (kk < 176) { p = g_AX2; off = xb + (kk - 160); }
                else               { p = g_B2;  off = (size_t)row * 128 + z * 64 + (kk - 176); }
                v = *(const float4*)&p[off];
            }
            int rloc = f >> 2, kq = (f & 3) * 4;
            As[kq + 0][rloc] = v.x; As[kq + 1][rloc] = v.y;
            As[kq + 2][rloc] = v.z; As[kq + 3][rloc] = v.w;
        }
        {
            int k = tt >> 4, cq = (tt & 15) * 4;
            int col = col0 + cq;
            float4 v = make_float4(0.f, 0.f, 0.f, 0.f);
            if (col < Nout) v = *(const float4*)&W[(size_t)(k0 + k) * Nout + col];
            *(float4*)&Bs[k][cq] = v;
        }
        __syncthreads();
#pragma unroll
        for (int k = 0; k < 16; k++) {
            float a0[4], a1[4], bv[4];
            *(float4*)a0 = *(const float4*)&As[k][rA];
            *(float4*)a1 = *(const float4*)&As[k][rA + 64];
            *(float4*)bv = *(const float4*)&Bs[k][cBl];
#pragma unroll
            for (int i = 0; i < 4; i++)
#pragma unroll
                for (int j = 0; j < 4; j++) {
                    acc[0][i][j] += a0[i] * bv[j];
                    acc[1][i][j] += a1[i] * bv[j];
                }
        }
        __syncthreads();
    }

#pragma unroll
    for (int rh = 0; rh < 2; rh++)
#pragma unroll
        for (int i = 0; i < 4; i++) {
            int row = row0 + rA + rh * 64 + i;
#pragma unroll
            for (int j = 0; j < 4; j++) {
                int col = col0 + cBl + j;
                if (col >= Nout) continue;
                float v = acc[rh][i][j] + bias[col];
                if (mode == 0) {
                    Out[(size_t)z * oB + (size_t)row * ldo + col] = tanhf(v);
                } else if (mode == 1) {
                    size_t ii = (size_t)row * 128 + z * 64 + col;
                    float s = g_S[ii] + DT_SUB * tanhf(v);
                    g_S[ii] = s;
                    split_bf(s, g_Shi[ii], g_Slo[ii]);
                    if (t >= 0) g_pre[(size_t)t * ((size_t)ROWSi * 128) + ii] = s;
                } else if (mode == 2) {
                    float g = 1.f / (1.f + expf(-v));
                    if (col < 64) {
                        size_t ii = (size_t)row * 128 + z * 64 + col;
                        float rh_v = g * g_S[ii];
                        g_RH[ii] = rh_v;
                        split_bf(rh_v, g_RHhi[ii], g_RHlo[ii]);
                    } else {
                        g_u[(size_t)row * 128 + z * 64 + (col - 64)] = g;
                    }
                } else if (mode == 3) {
                    float cc = tanhf(v);
                    size_t ii = (size_t)row * 128 + z * 64 + col;
                    float u = g_u[ii], h = g_S[ii];
                    float m = g_obs[((size_t)(row >> 10) * TTi + t) * NNi + (row & 1023)];
                    float hn = u * h + (1.f - u) * cc;
                    float s = h + m * (hn - h);
                    g_S[ii] = s;
                    split_bf(s, g_Shi[ii], g_Slo[ii]);
                } else if (mode == 4) {
                    float g = 1.f / (1.f + expf(-v));
                    Out[(size_t)row * 64 + col] =
                        g * g_pre[(size_t)ROWSi * 128 + (size_t)row * 128 + col];
                } else { // 5: final output, remap t-major -> b-major [8,39,1024,16]
                    int tp = row >> 13, bn = row & 8191;
                    int bb = bn >> 10, n = bn & 1023;
                    Out[(((size_t)bb * 39 + tp) * NNi + n) * 16 + col] = v;
                }
            }
        }
}

// ------------------- host orchestration -------------------
extern "C" void kernel_launch(void* const* d_in, const int* in_sizes, int n_in,
                              void* d_out, int out_size) {
    const float* values  = (const float*)d_in[0];
    const float* masks   = (const float*)d_in[1];
    const float* A       = (const float*)d_in[2];
    const float* h0      = (const float*)d_in[3];
    const float* z0      = (const float*)d_in[4];
    const float* gV_Wg   = (const float*)d_in[5];
    const float* gV_bg   = (const float*)d_in[6];
    const float* gV_Wc   = (const float*)d_in[7];
    const float* gV_bc   = (const float*)d_in[8];
    const float* gG_Wg   = (const float*)d_in[9];
    const float* gG_bg   = (const float*)d_in[10];
    const float* gG_Wc   = (const float*)d_in[11];
    const float* gG_bc   = (const float*)d_in[12];
    const float* oV_W0   = (const float*)d_in[13];
    const float* oV_b0   = (const float*)d_in[14];
    const float* oV_Wout = (const float*)d_in[15];
    const float* oV_bout = (const float*)d_in[16];
    const float* oG_W0   = (const float*)d_in[17];
    const float* oG_b0   = (const float*)d_in[18];
    const float* oG_Wout = (const float*)d_in[19];
    const float* oG_bout = (const float*)d_in[20];
    const float* Wz1     = (const float*)d_in[21];
    const float* bz1     = (const float*)d_in[22];
    const float* Wz2     = (const float*)d_in[23];
    const float* bz2     = (const float*)d_in[24];
    const float* Wz3     = (const float*)d_in[25];
    const float* bz3     = (const float*)d_in[26];
    const float* Wo      = (const float*)d_in[27];
    const float* bo      = (const float*)d_in[28];

    float *pA2, *pX, *pAX1, *pAX2, *pS, *pB1, *pB2, *pRH, *pH1, *pT1, *pT2, *pPre;
    bf16 *pAhi, *pAlo, *pA2hi, *pA2lo, *pShi, *pSlo, *pRHhi, *pRHlo;
    cudaGetSymbolAddress((void**)&pA2,  g_A2);
    cudaGetSymbolAddress((void**)&pX,   g_X);
    cudaGetSymbolAddress((void**)&pAX1, g_AX1);
    cudaGetSymbolAddress((void**)&pAX2, g_AX2);
    cudaGetSymbolAddress((void**)&pS,   g_S);
    cudaGetSymbolAddress((void**)&pB1,  g_B1);
    cudaGetSymbolAddress((void**)&pB2,  g_B2);
    cudaGetSymbolAddress((void**)&pRH,  g_RH);
    cudaGetSymbolAddress((void**)&pH1,  g_H1);
    cudaGetSymbolAddress((void**)&pT1,  g_T1);
    cudaGetSymbolAddress((void**)&pT2,  g_T2);
    cudaGetSymbolAddress((void**)&pPre, g_pre);
    cudaGetSymbolAddress((void**)&pAhi,  g_Ahi);
    cudaGetSymbolAddress((void**)&pAlo,  g_Alo);
    cudaGetSymbolAddress((void**)&pA2hi, g_A2hi);
    cudaGetSymbolAddress((void**)&pA2lo, g_A2lo);
    cudaGetSymbolAddress((void**)&pShi,  g_Shi);
    cudaGetSymbolAddress((void**)&pSlo,  g_Slo);
    cudaGetSymbolAddress((void**)&pRHhi, g_RHhi);
    cudaGetSymbolAddress((void**)&pRHlo, g_RHlo);

    const size_t sA = (size_t)NNi * NNi;
    const size_t sX = (size_t)TTi * NNi * DINi;
    const int HMMA_SMEM = 2 * STAGE_BYTES;   // 75776
    cudaFuncSetAttribute(gemmA_hmma, cudaFuncAttributeMaxDynamicSharedMemorySize, HMMA_SMEM);

    initX_k<<<1280, 256>>>((const float4*)values, (const float4*)masks);
    initS_k<<<4096, 256>>>(h0, z0);

    // Precompute (SIMT fp32): A2 = A@A ; AX1/AX2 for all steps
    gemmA_k<<<dim3(8, 8, 8), 256>>>(A, A, A, sA, NNi, 0, 1024, pA2, pA2, sA, NNi, 0);
    gemmA_k<<<dim3(8, 5, 16), 256>>>(A, pA2, pX, sX, 0, 1, 640, pAX1, pAX2, sX, 0, 1);
    // bf16 splits of A and A2 (constant across the loop)
    splitA_k<<<32768, 256>>>(A,   pAhi,  pAlo);
    splitA_k<<<32768, 256>>>(pA2, pA2hi, pA2lo);

    dim3 mmaG(8, 1, 16);

    for (int t = 0; t < TTi; t++) {
        for (int sub = 0; sub < 2; sub++) {
            gemmA_hmma<<<mmaG, 256, HMMA_SMEM>>>(pAhi, pAlo, pA2hi, pA2lo, pShi, pSlo, pB1, pB2);
            dense_k<<<dim3(64, 1, 2), 256>>>(pS, 0, 0,
                oV_W0, oG_W0, oV_b0, oG_b0, 192, 64, 0, -1,
                pH1, 64, (size_t)ROWSi * 64, 1, nullptr);
            dense_k<<<dim3(64, 1, 2), 256>>>(pH1, 64, (size_t)ROWSi * 64,
                oV_Wout, oG_Wout, oV_bout, oG_bout, 64, 64, 1, (sub == 1) ? t : -1,
                pS, 0, 0, 0, nullptr);
        }
        // GRU gate
        gemmA_hmma<<<mmaG, 256, HMMA_SMEM>>>(pAhi, pAlo, pA2hi, pA2lo, pShi, pSlo, pB1, pB2);
        dense_k<<<dim3(64, 2, 2), 256>>>(pS, 0, 0,
            gV_Wg, gG_Wg, gV_bg, gG_bg, 240, 128, 2, t, pS, 0, 0, 2, pS);
        // GRU candidate + blend
        gemmA_hmma<<<mmaG, 256, HMMA_SMEM>>>(pAhi, pAlo, pA2hi, pA2lo, pRHhi, pRHlo, pB1, pB2);
        dense_k<<<dim3(64, 1, 2), 256>>>(pS, 0, 0,
            gV_Wc, gG_Wc, gV_bc, gG_bc, 240, 64, 3, t, pS, 0, 0, 2, pRH);
    }

    // Output head over t = 1..39
    dense_k<<<dim3(2496, 1, 1), 256>>>(pPre + (size_t)ROWSi * 128 + 64, 128, 0,
        Wz1, Wz1, bz1, bz1, 64, 64, 0, -1, pT1, 64, 0, 0, nullptr);
    dense_k<<<dim3(2496, 1, 1), 256>>>(pT1, 64, 0,
        Wz2, Wz2, bz2, bz2, 64, 64, 0, -1, pT2, 64, 0, 0, nullptr);
    dense_k<<<dim3(2496, 1, 1), 256>>>(pT2, 64, 0,
        Wz3, Wz3, bz3, bz3, 64, 64, 4, -1, pT1, 64, 0, 0, nullptr);
    dense_k<<<dim3(2496, 1, 1), 256>>>(pT1, 64, 0,
        Wo, Wo, bo, bo, 64, 16, 5, -1, (float*)d_out, 16, 0, 0, nullptr);
}

// round 5
// speedup vs baseline: 2.0143x; 1.0593x over previous
#include <cuda_runtime.h>
#include <cuda_bf16.h>
#include <cstdint>

#define NNi   1024
#define BBi   8
#define TTi   40
#define DINi  16
#define ROWSi 8192
#define DT_SUB 0.025f

typedef __nv_bfloat16 bf16;

// ------------------- static scratch (no runtime allocation) -------------------
__device__ float g_A2 [(size_t)BBi*NNi*NNi];
__device__ float g_X  [(size_t)BBi*TTi*NNi*DINi];
__device__ float g_obs[(size_t)BBi*TTi*NNi];
__device__ float g_AX1[(size_t)BBi*TTi*NNi*DINi];
__device__ float g_AX2[(size_t)BBi*TTi*NNi*DINi];
__device__ float g_S  [(size_t)ROWSi*128];
__device__ float g_u  [(size_t)ROWSi*128];
__device__ float g_pre[(size_t)TTi*ROWSi*128];
__device__ float g_T1 [(size_t)39*ROWSi*64];
__device__ float g_T2 [(size_t)39*ROWSi*64];
// bf16 split operand twins
__device__ bf16 g_Ahi  [(size_t)BBi*NNi*NNi];
__device__ bf16 g_Alo  [(size_t)BBi*NNi*NNi];
__device__ bf16 g_A2hi [(size_t)BBi*NNi*NNi];
__device__ bf16 g_A2lo [(size_t)BBi*NNi*NNi];
__device__ bf16 g_Shi  [(size_t)ROWSi*128];
__device__ bf16 g_Slo  [(size_t)ROWSi*128];
__device__ bf16 g_RHhi [(size_t)ROWSi*128];
__device__ bf16 g_RHlo [(size_t)ROWSi*128];
__device__ bf16 g_B1hi [(size_t)ROWSi*128];
__device__ bf16 g_B1lo [(size_t)ROWSi*128];
__device__ bf16 g_B2hi [(size_t)ROWSi*128];
__device__ bf16 g_B2lo [(size_t)ROWSi*128];
__device__ bf16 g_Xhi  [(size_t)BBi*TTi*NNi*DINi];
__device__ bf16 g_Xlo  [(size_t)BBi*TTi*NNi*DINi];
__device__ bf16 g_AX1hi[(size_t)BBi*TTi*NNi*DINi];
__device__ bf16 g_AX1lo[(size_t)BBi*TTi*NNi*DINi];
__device__ bf16 g_AX2hi[(size_t)BBi*TTi*NNi*DINi];
__device__ bf16 g_AX2lo[(size_t)BBi*TTi*NNi*DINi];
__device__ bf16 g_H1hi [(size_t)2*ROWSi*64];
__device__ bf16 g_H1lo [(size_t)2*ROWSi*64];
__device__ bf16 g_zero_bf[16];                  // zero-initialized
// padded bf16 weight splits  [z][Kpad*Npad]
__device__ bf16 g_oW0hi  [2*192*64];
__device__ bf16 g_oW0lo  [2*192*64];
__device__ bf16 g_oWouthi[2*64*64];
__device__ bf16 g_oWoutlo[2*64*64];
__device__ bf16 g_gWghi  [2*256*128];
__device__ bf16 g_gWglo  [2*256*128];
__device__ bf16 g_gWchi  [2*256*64];
__device__ bf16 g_gWclo  [2*256*64];

// ------------------- asm helpers (plain sm_80+ features only) -------------------
__device__ __forceinline__ uint32_t smem_u32(const void* p) {
    uint32_t a;
    asm("{ .reg .u64 t; cvta.to.shared.u64 t, %1; cvt.u32.u64 %0, t; }" : "=r"(a) : "l"(p));
    return a;
}
__device__ __forceinline__ void ldm4(uint32_t* r, uint32_t a) {
    asm volatile("ldmatrix.sync.aligned.m8n8.x4.shared.b16 {%0,%1,%2,%3}, [%4];"
        : "=r"(r[0]), "=r"(r[1]), "=r"(r[2]), "=r"(r[3]) : "r"(a));
}
__device__ __forceinline__ void ldm4t(uint32_t* r, uint32_t a) {
    asm volatile("ldmatrix.sync.aligned.m8n8.x4.trans.shared.b16 {%0,%1,%2,%3}, [%4];"
        : "=r"(r[0]), "=r"(r[1]), "=r"(r[2]), "=r"(r[3]) : "r"(a));
}
__device__ __forceinline__ void mma_bf(float* c, const uint32_t* a, uint32_t b0, uint32_t b1) {
    asm volatile("mma.sync.aligned.m16n8k16.row.col.f32.bf16.bf16.f32 "
        "{%0,%1,%2,%3}, {%4,%5,%6,%7}, {%8,%9}, {%0,%1,%2,%3};"
        : "+f"(c[0]), "+f"(c[1]), "+f"(c[2]), "+f"(c[3])
        : "r"(a[0]), "r"(a[1]), "r"(a[2]), "r"(a[3]), "r"(b0), "r"(b1));
}
__device__ __forceinline__ void cpa16(uint32_t sm, const void* gm) {
    asm volatile("cp.async.cg.shared.global [%0], [%1], 16;"
        :: "r"(sm), "l"(__cvta_generic_to_global(gm)));
}
#define CP_COMMIT() asm volatile("cp.async.commit_group;" ::: "memory")
#define CP_WAIT0()  asm volatile("cp.async.wait_group 0;" ::: "memory")
#define CP_WAIT1()  asm volatile("cp.async.wait_group 1;" ::: "memory")

__device__ __forceinline__ void split_bf(float v, bf16& h, bf16& l) {
    h = __float2bfloat16_rn(v);
    l = __float2bfloat16_rn(v - __bfloat162float(h));
}

// ------------------- init / split kernels -------------------
__global__ void initX_k(const float4* __restrict__ v, const float4* __restrict__ m) {
    int i = blockIdx.x * 256 + threadIdx.x;   // [0, 327680)
    float s = 0.f;
#pragma unroll
    for (int q = 0; q < 4; q++) {
        float4 vv = v[i * 4 + q], mm = m[i * 4 + q];
        s += fabsf(mm.x) + fabsf(mm.y) + fabsf(mm.z) + fabsf(mm.w);
        float4 x = make_float4(vv.x * mm.x, vv.y * mm.y, vv.z * mm.z, vv.w * mm.w);
        ((float4*)g_X)[i * 4 + q] = x;
        size_t o = (size_t)i * 16 + q * 4;
        split_bf(x.x, g_Xhi[o + 0], g_Xlo[o + 0]);
        split_bf(x.y, g_Xhi[o + 1], g_Xlo[o + 1]);
        split_bf(x.z, g_Xhi[o + 2], g_Xlo[o + 2]);
        split_bf(x.w, g_Xhi[o + 3], g_Xlo[o + 3]);
    }
    g_obs[i] = (s > 1e-4f) ? 1.f : 0.f;
}
__global__ void initS_k(const float* __restrict__ h0, const float* __restrict__ z0) {
    int i = blockIdx.x * 256 + threadIdx.x;
    int c = i & 127;
    float v = (c < 64) ? h0[c] : z0[c - 64];
    g_S[i] = v;
    split_bf(v, g_Shi[i], g_Slo[i]);
}
__global__ void splitA_k(const float* __restrict__ src, bf16* __restrict__ hi, bf16* __restrict__ lo) {
    size_t i = (size_t)blockIdx.x * 256 + threadIdx.x;
    split_bf(src[i], hi[i], lo[i]);
}
__global__ void splitW_k(const float* __restrict__ src, bf16* __restrict__ hi, bf16* __restrict__ lo,
                         int K, int N, int Npad) {
    int i = blockIdx.x * 256 + threadIdx.x;   // over Kpad*Npad
    int k = i / Npad, n = i - k * Npad;
    float v = (k < K && n < N) ? src[k * N + n] : 0.f;
    split_bf(v, hi[i], lo[i]);
}

// ------------------- HMMA bf16 3-product diffusion GEMM -------------------
#define STAGE_BYTES 37888
#define A_LO_OFF    10240
#define B_OFF       20480
#define B_LO_OFF    8704

__device__ __forceinline__ void hmma_load_stage(
    uint32_t so, int k0, int t, int row0,
    const bf16* __restrict__ Ah, const bf16* __restrict__ Al,
    const bf16* __restrict__ Bh, const bf16* __restrict__ Bl)
{
#pragma unroll
    for (int i = 0; i < 4; i++) {
        int c = t + i * 256;
        int arr = c >> 9, cc = c & 511, row = cc >> 2, seg = cc & 3;
        const bf16* g = (arr ? Al : Ah) + (size_t)(row0 + row) * NNi + k0 + seg * 8;
        cpa16(so + arr * A_LO_OFF + row * 80 + seg * 16, g);
    }
#pragma unroll
    for (int i = 0; i < 4; i++) {
        int c = t + i * 256;
        int arr = c >> 9, cc = c & 511, k = cc >> 4, seg = cc & 15;
        const bf16* g = (arr ? Bl : Bh) + (size_t)(k0 + k) * 128 + seg * 8;
        cpa16(so + B_OFF + arr * B_LO_OFF + k * 272 + seg * 16, g);
    }
    CP_COMMIT();
}

__global__ void __launch_bounds__(256, 2) gemmA_hmma(
    const bf16* __restrict__ Ahi1, const bf16* __restrict__ Alo1,
    const bf16* __restrict__ Ahi2, const bf16* __restrict__ Alo2,
    const bf16* __restrict__ Bhi, const bf16* __restrict__ Blo,
    bf16* __restrict__ O1hi, bf16* __restrict__ O1lo,
    bf16* __restrict__ O2hi, bf16* __restrict__ O2lo)
{
    extern __shared__ char smraw[];
    int bz = blockIdx.z;
    int b = bz & 7, hop = bz >> 3;
    const bf16* Ah = (hop ? Ahi2 : Ahi1) + (size_t)b * NNi * NNi;
    const bf16* Al = (hop ? Alo2 : Alo1) + (size_t)b * NNi * NNi;
    const bf16* Bh = Bhi + (size_t)b * NNi * 128;
    const bf16* Bl = Blo + (size_t)b * NNi * 128;
    bf16* Ohi = (hop ? O2hi : O1hi) + (size_t)b * NNi * 128;
    bf16* Olo = (hop ? O2lo : O1lo) + (size_t)b * NNi * 128;
    int row0 = blockIdx.x * 128;

    int t = threadIdx.x, wid = t >> 5, lane = t & 31;
    int wm = (wid & 3) * 32, wn = (wid >> 2) * 64;
    uint32_t sbase = smem_u32(smraw);

    float acc[2][8][4];
#pragma unroll
    for (int mt = 0; mt < 2; mt++)
#pragma unroll
        for (int nt = 0; nt < 8; nt++)
#pragma unroll
            for (int q = 0; q < 4; q++) acc[mt][nt][q] = 0.f;

    uint32_t lmRow  = lane & 15;
    uint32_t lmColB = (lane >> 4) * 16;

    hmma_load_stage(sbase, 0, t, row0, Ah, Al, Bh, Bl);

    for (int kt = 0; kt < 32; kt++) {
        if (kt < 31)
            hmma_load_stage(sbase + ((kt + 1) & 1) * STAGE_BYTES, (kt + 1) * 32, t, row0, Ah, Al, Bh, Bl);
        if (kt < 31) { CP_WAIT1(); } else { CP_WAIT0(); }
        __syncthreads();

        uint32_t so = sbase + (kt & 1) * STAGE_BYTES;
#pragma unroll
        for (int ks = 0; ks < 2; ks++) {
            uint32_t ah[2][4], al[2][4];
#pragma unroll
            for (int mt = 0; mt < 2; mt++) {
                uint32_t ad = so + (wm + mt * 16 + lmRow) * 80 + ks * 32 + lmColB;
                ldm4(ah[mt], ad);
                ldm4(al[mt], ad + A_LO_OFF);
            }
#pragma unroll
            for (int np = 0; np < 4; np++) {
                uint32_t bd = so + B_OFF + (ks * 16 + lmRow) * 272 + (wn + np * 16) * 2 + lmColB;
                uint32_t bh[4], bl[4];
                ldm4t(bh, bd);
                ldm4t(bl, bd + B_LO_OFF);
#pragma unroll
                for (int mt = 0; mt < 2; mt++) {
                    mma_bf(acc[mt][2 * np],     ah[mt], bh[0], bh[1]);
                    mma_bf(acc[mt][2 * np + 1], ah[mt], bh[2], bh[3]);
                    mma_bf(acc[mt][2 * np],     ah[mt], bl[0], bl[1]);
                    mma_bf(acc[mt][2 * np + 1], ah[mt], bl[2], bl[3]);
                    mma_bf(acc[mt][2 * np],     al[mt], bh[0], bh[1]);
                    mma_bf(acc[mt][2 * np + 1], al[mt], bh[2], bh[3]);
                }
            }
        }
        __syncthreads();
    }

    int gr = lane >> 2, gc = (lane & 3) * 2;
#pragma unroll
    for (int mt = 0; mt < 2; mt++)
#pragma unroll
        for (int nt = 0; nt < 8; nt++) {
            int r = row0 + wm + mt * 16 + gr;
            int c = wn + nt * 8 + gc;
            bf16 h0, l0, h1, l1;
            split_bf(acc[mt][nt][0], h0, l0); split_bf(acc[mt][nt][1], h1, l1);
            *(__nv_bfloat162*)&Ohi[(size_t)r * 128 + c] = __halves2bfloat162(h0, h1);
            *(__nv_bfloat162*)&Olo[(size_t)r * 128 + c] = __halves2bfloat162(l0, l1);
            split_bf(acc[mt][nt][2], h0, l0); split_bf(acc[mt][nt][3], h1, l1);
            *(__nv_bfloat162*)&Ohi[(size_t)(r + 8) * 128 + c] = __halves2bfloat162(h0, h1);
            *(__nv_bfloat162*)&Olo[(size_t)(r + 8) * 128 + c] = __halves2bfloat162(l0, l1);
        }
}

// ------------------- SIMT batched A-GEMM (precompute only) -------------------
__global__ __launch_bounds__(256, 2) void gemmA_k(
    const float* __restrict__ Aop1, const float* __restrict__ Aop2,
    const float* __restrict__ Bsrc, size_t sB, int ldb, int bmode, int C,
    float* __restrict__ O1, float* __restrict__ O2, size_t sO, int ldo, int omode)
{
    int bz = blockIdx.z;
    int b = bz & 7, hop = bz >> 3;
    const float* Ab = (hop ? Aop2 : Aop1) + (size_t)b * NNi * NNi;
    const float* Bb = Bsrc + (size_t)b * sB;
    float* Ob = (hop ? O2 : O1) + (size_t)b * sO;
    int row0 = blockIdx.x * 128, col0 = blockIdx.y * 128;

    __shared__ float As[16][128];
    __shared__ float Bs[16][128];

    int t  = threadIdx.x;
    int tx = t & 15, ty = t >> 4;
    int rA = ty * 4, cB = tx * 4;

    float acc[2][2][4][4];
#pragma unroll
    for (int a = 0; a < 2; a++)
#pragma unroll
        for (int c = 0; c < 2; c++)
#pragma unroll
            for (int i = 0; i < 4; i++)
#pragma unroll
                for (int j = 0; j < 4; j++) acc[a][c][i][j] = 0.f;

    for (int k0 = 0; k0 < NNi; k0 += 16) {
#pragma unroll
        for (int i = 0; i < 2; i++) {
            int f = t + i * 256;
            int row = f >> 2, kq = (f & 3) * 4;
            float4 v = *(const float4*)&Ab[(size_t)(row0 + row) * NNi + k0 + kq];
            As[kq + 0][row] = v.x; As[kq + 1][row] = v.y;
            As[kq + 2][row] = v.z; As[kq + 3][row] = v.w;
        }
#pragma unroll
        for (int i = 0; i < 2; i++) {
            int f = t + i * 256;
            int k = f >> 5, cq = (f & 31) * 4;
            int col = col0 + cq;
            size_t off;
            if (bmode == 1) off = (size_t)(k0 + k) * 16 + (size_t)(col >> 4) * 16384 + (col & 15);
            else            off = (size_t)(k0 + k) * ldb + col;
            *(float4*)&Bs[k][cq] = *(const float4*)&Bb[off];
        }
        __syncthreads();
#pragma unroll
        for (int k = 0; k < 16; k++) {
            float a[2][4], bb[2][4];
            *(float4*)a[0]  = *(const float4*)&As[k][rA];
            *(float4*)a[1]  = *(const float4*)&As[k][rA + 64];
            *(float4*)bb[0] = *(const float4*)&Bs[k][cB];
            *(float4*)bb[1] = *(const float4*)&Bs[k][cB + 64];
#pragma unroll
            for (int rh = 0; rh < 2; rh++)
#pragma unroll
                for (int ch = 0; ch < 2; ch++)
#pragma unroll
                    for (int i = 0; i < 4; i++)
#pragma unroll
                        for (int j = 0; j < 4; j++)
                            acc[rh][ch][i][j] += a[rh][i] * bb[ch][j];
        }
        __syncthreads();
    }
#pragma unroll
    for (int rh = 0; rh < 2; rh++)
#pragma unroll
        for (int i = 0; i < 4; i++) {
            int row = row0 + rA + rh * 64 + i;
#pragma unroll
            for (int ch = 0; ch < 2; ch++) {
                int col = col0 + cB + ch * 64;
                size_t off;
                if (omode == 1) off = (size_t)row * 16 + (size_t)(col >> 4) * 16384 + (col & 15);
                else            off = (size_t)row * ldo + col;
                *(float4*)&Ob[off] = *(float4*)&acc[rh][ch][i][0];
            }
        }
}

// ------------------- HMMA dense GEMM with fused gathers + epilogues -------------------
// afmt 1: ODE feats [S|B1|B2] K=192; afmt 2: GRU feats [X|H|AX1|B1|AX2|B2] K=240(pad256);
// afmt 3: A = H1 bf16 pair, lda 64 per cell.
// modes: 0 H1=tanh | 1 Euler S+=dt*tanh (+pre[t]) | 2 gate r*h->RH, u | 3 cand blend->S
#define DH_A_STRIDE 80
#define DH_ALO_OFF  10240
#define DH_B_OFF    20480
#define DH_B_STRIDE 144
#define DH_BLO_OFF  4608
#define DH_STAGE    29696

__device__ __forceinline__ void dh_load_stage(
    uint32_t so, int k0, int row0, int z, int t, int col0, int Kdim, int afmt,
    const bf16* __restrict__ Hhi, const bf16* __restrict__ Hlo,
    const bf16* __restrict__ Whi, const bf16* __restrict__ Wlo, int Npad)
{
#pragma unroll
    for (int i = 0; i < 4; i++) {          // A tile: 128 rows x 32 k, hi+lo
        int c = threadIdx.x + i * 256;
        int arr = c >> 9, cc = c & 511;
        int row = cc >> 2, seg = cc & 3;
        int kk = k0 + seg * 8;
        int grow = row0 + row;
        const bf16* src; size_t off;
        if (afmt == 3) {
            src = arr ? Hlo : Hhi;
            off = ((size_t)z * ROWSi + grow) * 64 + kk;
        } else if (afmt == 1) {
            const bf16 *hi, *lo; int kloc;
            if (kk < 64)       { hi = g_Shi;  lo = g_Slo;  kloc = kk; }
            else if (kk < 128) { hi = g_B1hi; lo = g_B1lo; kloc = kk - 64; }
            else               { hi = g_B2hi; lo = g_B2lo; kloc = kk - 128; }
            src = arr ? lo : hi;
            off = (size_t)grow * 128 + z * 64 + kloc;
        } else {               // afmt 2
            if (kk >= Kdim) { src = g_zero_bf; off = 0; }
            else {
                int bb = grow >> 10, n = grow & 1023;
                size_t xb = (((size_t)bb * TTi + t) * NNi + n) * 16;
                const bf16 *hi, *lo; size_t o2;
                if (kk < 16)       { hi = g_Xhi;   lo = g_Xlo;   o2 = xb + kk; }
                else if (kk < 80)  { hi = Hhi;     lo = Hlo;     o2 = (size_t)grow * 128 + z * 64 + (kk - 16); }
                else if (kk < 96)  { hi = g_AX1hi; lo = g_AX1lo; o2 = xb + (kk - 80); }
                else if (kk < 160) { hi = g_B1hi;  lo = g_B1lo;  o2 = (size_t)grow * 128 + z * 64 + (kk - 96); }
                else if (kk < 176) { hi = g_AX2hi; lo = g_AX2lo; o2 = xb + (kk - 160); }
                else               { hi = g_B2hi;  lo = g_B2lo;  o2 = (size_t)grow * 128 + z * 64 + (kk - 176); }
                src = arr ? lo : hi; off = o2;
            }
        }
        cpa16(so + arr * DH_ALO_OFF + row * DH_A_STRIDE + seg * 16, src + off);
    }
#pragma unroll
    for (int i = 0; i < 2; i++) {          // B tile: 32 k x 64 cols, hi+lo
        int c = threadIdx.x + i * 256;
        int arr = c >> 8, cc = c & 255;
        int k = cc >> 3, seg = cc & 7;
        const bf16* w = (arr ? Wlo : Whi) + (size_t)(k0 + k) * Npad + col0 + seg * 8;
        cpa16(so + DH_B_OFF + arr * DH_BLO_OFF + k * DH_B_STRIDE + seg * 16, w);
    }
    CP_COMMIT();
}

__device__ __forceinline__ void dh_epi(int mode, int z, int t, int row, int col, float v) {
    if (mode == 0) {
        float vt = tanhf(v);
        size_t ii = ((size_t)z * ROWSi + row) * 64 + col;
        split_bf(vt, g_H1hi[ii], g_H1lo[ii]);
    } else if (mode == 1) {
        size_t ii = (size_t)row * 128 + z * 64 + col;
        float s = g_S[ii] + DT_SUB * tanhf(v);
        g_S[ii] = s;
        split_bf(s, g_Shi[ii], g_Slo[ii]);
        if (t >= 0) g_pre[(size_t)t * ((size_t)ROWSi * 128) + ii] = s;
    } else if (mode == 2) {
        float g = 1.f / (1.f + expf(-v));
        if (col < 64) {
            size_t ii = (size_t)row * 128 + z * 64 + col;
            float rh = g * g_S[ii];
            split_bf(rh, g_RHhi[ii], g_RHlo[ii]);
        } else {
            g_u[(size_t)row * 128 + z * 64 + (col - 64)] = g;
        }
    } else { // 3
        float cc = tanhf(v);
        size_t ii = (size_t)row * 128 + z * 64 + col;
        float u = g_u[ii], h = g_S[ii];
        float m = g_obs[((size_t)(row >> 10) * TTi + t) * NNi + (row & 1023)];
        float hn = u * h + (1.f - u) * cc;
        float s = h + m * (hn - h);
        g_S[ii] = s;
        split_bf(s, g_Shi[ii], g_Slo[ii]);
    }
}

__global__ void __launch_bounds__(256, 2) denseH_k(
    int afmt, int Kdim, int nkt, int mode, int t,
    const bf16* __restrict__ Hhi, const bf16* __restrict__ Hlo,
    const bf16* __restrict__ W0hi, const bf16* __restrict__ W0lo,
    const bf16* __restrict__ W1hi, const bf16* __restrict__ W1lo, int Npad,
    const float* __restrict__ bias0, const float* __restrict__ bias1)
{
    extern __shared__ char smraw[];
    int z = blockIdx.z;
    int row0 = blockIdx.x * 128;
    int col0 = blockIdx.y * 64;
    const bf16* Whi = z ? W1hi : W0hi;
    const bf16* Wlo = z ? W1lo : W0lo;
    const float* bias = z ? bias1 : bias0;

    int tid = threadIdx.x, wid = tid >> 5, lane = tid & 31;
    int wm = (wid & 3) * 32, wn = (wid >> 2) * 32;
    uint32_t sb = smem_u32(smraw);
    uint32_t lmRow = lane & 15, lmColB = (lane >> 4) * 16;

    float acc[2][4][4];
#pragma unroll
    for (int mt = 0; mt < 2; mt++)
#pragma unroll
        for (int nt = 0; nt < 4; nt++)
#pragma unroll
            for (int q = 0; q < 4; q++) acc[mt][nt][q] = 0.f;

    dh_load_stage(sb, 0, row0, z, t, col0, Kdim, afmt, Hhi, Hlo, Whi, Wlo, Npad);

    for (int kt = 0; kt < nkt; kt++) {
        if (kt + 1 < nkt)
            dh_load_stage(sb + ((kt + 1) & 1) * DH_STAGE, (kt + 1) * 32, row0, z, t, col0,
                          Kdim, afmt, Hhi, Hlo, Whi, Wlo, Npad);
        if (kt + 1 < nkt) { CP_WAIT1(); } else { CP_WAIT0(); }
        __syncthreads();

        uint32_t so = sb + (kt & 1) * DH_STAGE;
#pragma unroll
        for (int ks = 0; ks < 2; ks++) {
            uint32_t ah[2][4], al[2][4];
#pragma unroll
            for (int mt = 0; mt < 2; mt++) {
                uint32_t ad = so + (wm + mt * 16 + lmRow) * DH_A_STRIDE + ks * 32 + lmColB;
                ldm4(ah[mt], ad);
                ldm4(al[mt], ad + DH_ALO_OFF);
            }
#pragma unroll
            for (int np = 0; np < 2; np++) {
                uint32_t bd = so + DH_B_OFF + (ks * 16 + lmRow) * DH_B_STRIDE + (wn + np * 16) * 2 + lmColB;
                uint32_t bh[4], bl[4];
                ldm4t(bh, bd);
                ldm4t(bl, bd + DH_BLO_OFF);
#pragma unroll
                for (int mt = 0; mt < 2; mt++) {
                    mma_bf(acc[mt][2 * np],     ah[mt], bh[0], bh[1]);
                    mma_bf(acc[mt][2 * np + 1], ah[mt], bh[2], bh[3]);
                    mma_bf(acc[mt][2 * np],     ah[mt], bl[0], bl[1]);
                    mma_bf(acc[mt][2 * np + 1], ah[mt], bl[2], bl[3]);
                    mma_bf(acc[mt][2 * np],     al[mt], bh[0], bh[1]);
                    mma_bf(acc[mt][2 * np + 1], al[mt], bh[2], bh[3]);
                }
            }
        }
        __syncthreads();
    }

    int gr = lane >> 2, gc = (lane & 3) * 2;
#pragma unroll
    for (int mt = 0; mt < 2; mt++)
#pragma unroll
        for (int nt = 0; nt < 4; nt++) {
            int r = row0 + wm + mt * 16 + gr;
            int c = col0 + wn + nt * 8 + gc;
            dh_epi(mode, z, t, r,     c,     acc[mt][nt][0] + bias[c]);
            dh_epi(mode, z, t, r,     c + 1, acc[mt][nt][1] + bias[c + 1]);
            dh_epi(mode, z, t, r + 8, c,     acc[mt][nt][2] + bias[c]);
            dh_epi(mode, z, t, r + 8, c + 1, acc[mt][nt][3] + bias[c + 1]);
        }
}

// ------------------- SIMT dense (output head only) -------------------
// modes: 0 tanh->Out | 4 sigmoid*hpre->Out | 5 plain->d_out remapped
__global__ __launch_bounds__(256, 2) void dense_k(
    const float* __restrict__ Ain, int lda,
    const float* __restrict__ W, const float* __restrict__ bias,
    int Kdim, int Nout, int mode,
    float* __restrict__ Out, int ldo)
{
    int row0 = blockIdx.x * 128, col0 = 0;

    __shared__ float As[16][128];
    __shared__ float Bs[16][64];

    int tt = threadIdx.x;
    int tx = tt & 15, ty = tt >> 4;
    int rA = ty * 4, cBl = tx * 4;

    float acc[2][4][4];
#pragma unroll
    for (int a = 0; a < 2; a++)
#pragma unroll
        for (int i = 0; i < 4; i++)
#pragma unroll
            for (int j = 0; j < 4; j++) acc[a][i][j] = 0.f;

    for (int k0 = 0; k0 < Kdim; k0 += 16) {
#pragma unroll
        for (int i = 0; i < 2; i++) {
            int f = tt + i * 256;
            int row = f >> 2, kq = (f & 3) * 4;
            float4 v = *(const float4*)&Ain[(size_t)(row0 + row) * lda + k0 + kq];
            As[kq + 0][row] = v.x; As[kq + 1][row] = v.y;
            As[kq + 2][row] = v.z; As[kq + 3][row] = v.w;
        }
        {
            int k = tt >> 4, cq = (tt & 15) * 4;
            int col = col0 + cq;
            float4 v = make_float4(0.f, 0.f, 0.f, 0.f);
            if (col < Nout) v = *(const float4*)&W[(size_t)(k0 + k) * Nout + col];
            *(float4*)&Bs[k][cq] = v;
        }
        __syncthreads();
#pragma unroll
        for (int k = 0; k < 16; k++) {
            float a0[4], a1[4], bv[4];
            *(float4*)a0 = *(const float4*)&As[k][rA];
            *(float4*)a1 = *(const float4*)&As[k][rA + 64];
            *(float4*)bv = *(const float4*)&Bs[k][cBl];
#pragma unroll
            for (int i = 0; i < 4; i++)
#pragma unroll
                for (int j = 0; j < 4; j++) {
                    acc[0][i][j] += a0[i] * bv[j];
                    acc[1][i][j] += a1[i] * bv[j];
                }
        }
        __syncthreads();
    }

#pragma unroll
    for (int rh = 0; rh < 2; rh++)
#pragma unroll
        for (int i = 0; i < 4; i++) {
            int row = row0 + rA + rh * 64 + i;
#pragma unroll
            for (int j = 0; j < 4; j++) {
                int col = col0 + cBl + j;
                if (col >= Nout) continue;
                float v = acc[rh][i][j] + bias[col];
                if (mode == 0) {
                    Out[(size_t)row * ldo + col] = tanhf(v);
                } else if (mode == 4) {
                    float g = 1.f / (1.f + expf(-v));
                    Out[(size_t)row * 64 + col] =
                        g * g_pre[(size_t)ROWSi * 128 + (size_t)row * 128 + col];
                } else { // 5
                    int tp = row >> 13, bn = row & 8191;
                    int bb = bn >> 10, n = bn & 1023;
                    Out[(((size_t)bb * 39 + tp) * NNi + n) * 16 + col] = v;
                }
            }
        }
}

// ------------------- host orchestration -------------------
extern "C" void kernel_launch(void* const* d_in, const int* in_sizes, int n_in,
                              void* d_out, int out_size) {
    const float* values  = (const float*)d_in[0];
    const float* masks   = (const float*)d_in[1];
    const float* A       = (const float*)d_in[2];
    const float* h0      = (const float*)d_in[3];
    const float* z0      = (const float*)d_in[4];
    const float* gV_Wg   = (const float*)d_in[5];
    const float* gV_bg   = (const float*)d_in[6];
    const float* gV_Wc   = (const float*)d_in[7];
    const float* gV_bc   = (const float*)d_in[8];
    const float* gG_Wg   = (const float*)d_in[9];
    const float* gG_bg   = (const float*)d_in[10];
    const float* gG_Wc   = (const float*)d_in[11];
    const float* gG_bc   = (const float*)d_in[12];
    const float* oV_W0   = (const float*)d_in[13];
    const float* oV_b0   = (const float*)d_in[14];
    const float* oV_Wout = (const float*)d_in[15];
    const float* oV_bout = (const float*)d_in[16];
    const float* oG_W0   = (const float*)d_in[17];
    const float* oG_b0   = (const float*)d_in[18];
    const float* oG_Wout = (const float*)d_in[19];
    const float* oG_bout = (const float*)d_in[20];
    const float* Wz1     = (const float*)d_in[21];
    const float* bz1     = (const float*)d_in[22];
    const float* Wz2     = (const float*)d_in[23];
    const float* bz2     = (const float*)d_in[24];
    const float* Wz3     = (const float*)d_in[25];
    const float* bz3     = (const float*)d_in[26];
    const float* Wo      = (const float*)d_in[27];
    const float* bo      = (const float*)d_in[28];

    float *pA2, *pX, *pAX1, *pAX2, *pT1, *pT2, *pPre;
    bf16 *pAhi, *pAlo, *pA2hi, *pA2lo, *pShi, *pSlo, *pRHhi, *pRHlo;
    bf16 *pB1hi, *pB1lo, *pB2hi, *pB2lo, *pH1hi, *pH1lo;
    bf16 *pAX1hi, *pAX1lo, *pAX2hi, *pAX2lo;
    bf16 *pOW0hi, *pOW0lo, *pOWouthi, *pOWoutlo, *pGWghi, *pGWglo, *pGWchi, *pGWclo;
    cudaGetSymbolAddress((void**)&pA2,   g_A2);
    cudaGetSymbolAddress((void**)&pX,    g_X);
    cudaGetSymbolAddress((void**)&pAX1,  g_AX1);
    cudaGetSymbolAddress((void**)&pAX2,  g_AX2);
    cudaGetSymbolAddress((void**)&pT1,   g_T1);
    cudaGetSymbolAddress((void**)&pT2,   g_T2);
    cudaGetSymbolAddress((void**)&pPre,  g_pre);
    cudaGetSymbolAddress((void**)&pAhi,  g_Ahi);
    cudaGetSymbolAddress((void**)&pAlo,  g_Alo);
    cudaGetSymbolAddress((void**)&pA2hi, g_A2hi);
    cudaGetSymbolAddress((void**)&pA2lo, g_A2lo);
    cudaGetSymbolAddress((void**)&pShi,  g_Shi);
    cudaGetSymbolAddress((void**)&pSlo,  g_Slo);
    cudaGetSymbolAddress((void**)&pRHhi, g_RHhi);
    cudaGetSymbolAddress((void**)&pRHlo, g_RHlo);
    cudaGetSymbolAddress((void**)&pB1hi, g_B1hi);
    cudaGetSymbolAddress((void**)&pB1lo, g_B1lo);
    cudaGetSymbolAddress((void**)&pB2hi, g_B2hi);
    cudaGetSymbolAddress((void**)&pB2lo, g_B2lo);
    cudaGetSymbolAddress((void**)&pH1hi, g_H1hi);
    cudaGetSymbolAddress((void**)&pH1lo, g_H1lo);
    cudaGetSymbolAddress((void**)&pAX1hi, g_AX1hi);
    cudaGetSymbolAddress((void**)&pAX1lo, g_AX1lo);
    cudaGetSymbolAddress((void**)&pAX2hi, g_AX2hi);
    cudaGetSymbolAddress((void**)&pAX2lo, g_AX2lo);
    cudaGetSymbolAddress((void**)&pOW0hi,   g_oW0hi);
    cudaGetSymbolAddress((void**)&pOW0lo,   g_oW0lo);
    cudaGetSymbolAddress((void**)&pOWouthi, g_oWouthi);
    cudaGetSymbolAddress((void**)&pOWoutlo, g_oWoutlo);
    cudaGetSymbolAddress((void**)&pGWghi,   g_gWghi);
    cudaGetSymbolAddress((void**)&pGWglo,   g_gWglo);
    cudaGetSymbolAddress((void**)&pGWchi,   g_gWchi);
    cudaGetSymbolAddress((void**)&pGWclo,   g_gWclo);

    const size_t sA = (size_t)NNi * NNi;
    const size_t sX = (size_t)TTi * NNi * DINi;
    const int HMMA_SMEM = 2 * STAGE_BYTES;   // 75776
    const int DH_SMEM   = 2 * DH_STAGE;      // 59392
    cudaFuncSetAttribute(gemmA_hmma, cudaFuncAttributeMaxDynamicSharedMemorySize, HMMA_SMEM);
    cudaFuncSetAttribute(denseH_k,   cudaFuncAttributeMaxDynamicSharedMemorySize, DH_SMEM);

    initX_k<<<1280, 256>>>((const float4*)values, (const float4*)masks);
    initS_k<<<4096, 256>>>(h0, z0);

    // Precompute (SIMT fp32): A2 = A@A ; AX1/AX2 all steps
    gemmA_k<<<dim3(8, 8, 8), 256>>>(A, A, A, sA, NNi, 0, 1024, pA2, pA2, sA, NNi, 0);
    gemmA_k<<<dim3(8, 5, 16), 256>>>(A, pA2, pX, sX, 0, 1, 640, pAX1, pAX2, sX, 0, 1);
    // bf16 splits (one-time)
    splitA_k<<<32768, 256>>>(A,    pAhi,  pAlo);
    splitA_k<<<32768, 256>>>(pA2,  pA2hi, pA2lo);
    splitA_k<<<20480, 256>>>(pAX1, pAX1hi, pAX1lo);
    splitA_k<<<20480, 256>>>(pAX2, pAX2hi, pAX2lo);
    splitW_k<<<48, 256>>>(oV_W0,   pOW0hi,           pOW0lo,           192, 64, 64);
    splitW_k<<<48, 256>>>(oG_W0,   pOW0hi + 12288,   pOW0lo + 12288,   192, 64, 64);
    splitW_k<<<16, 256>>>(oV_Wout, pOWouthi,         pOWoutlo,         64, 64, 64);
    splitW_k<<<16, 256>>>(oG_Wout, pOWouthi + 4096,  pOWoutlo + 4096,  64, 64, 64);
    splitW_k<<<128, 256>>>(gV_Wg,  pGWghi,           pGWglo,           240, 128, 128);
    splitW_k<<<128, 256>>>(gG_Wg,  pGWghi + 32768,   pGWglo + 32768,   240, 128, 128);
    splitW_k<<<64, 256>>>(gV_Wc,   pGWchi,           pGWclo,           240, 64, 64);
    splitW_k<<<64, 256>>>(gG_Wc,   pGWchi + 16384,   pGWclo + 16384,   240, 64, 64);

    dim3 mmaG(8, 1, 16);

    for (int t = 0; t < TTi; t++) {
        for (int sub = 0; sub < 2; sub++) {
            gemmA_hmma<<<mmaG, 256, HMMA_SMEM>>>(pAhi, pAlo, pA2hi, pA2lo, pShi, pSlo,
                                                 pB1hi, pB1lo, pB2hi, pB2lo);
            denseH_k<<<dim3(64, 1, 2), 256, DH_SMEM>>>(1, 192, 6, 0, -1,
                nullptr, nullptr, pOW0hi, pOW0lo, pOW0hi + 12288, pOW0lo + 12288, 64,
                oV_b0, oG_b0);
            denseH_k<<<dim3(64, 1, 2), 256, DH_SMEM>>>(3, 64, 2, 1, (sub == 1) ? t : -1,
                pH1hi, pH1lo, pOWouthi, pOWoutlo, pOWouthi + 4096, pOWoutlo + 4096, 64,
                oV_bout, oG_bout);
        }
        if (t < TTi - 1) {   // last step's GRU outputs are never read
            gemmA_hmma<<<mmaG, 256, HMMA_SMEM>>>(pAhi, pAlo, pA2hi, pA2lo, pShi, pSlo,
                                                 pB1hi, pB1lo, pB2hi, pB2lo);
            denseH_k<<<dim3(64, 2, 2), 256, DH_SMEM>>>(2, 240, 8, 2, t,
                pShi, pSlo, pGWghi, pGWglo, pGWghi + 32768, pGWglo + 32768, 128,
                gV_bg, gG_bg);
            gemmA_hmma<<<mmaG, 256, HMMA_SMEM>>>(pAhi, pAlo, pA2hi, pA2lo, pRHhi, pRHlo,
                                                 pB1hi, pB1lo, pB2hi, pB2lo);
            denseH_k<<<dim3(64, 1, 2), 256, DH_SMEM>>>(2, 240, 8, 3, t,
                pRHhi, pRHlo, pGWchi, pGWclo, pGWchi + 16384, pGWclo + 16384, 64,
                gV_bc, gG_bc);
        }
    }

    // Output head over t = 1..39 (SIMT; ~10 GF total)
    dense_k<<<2496, 256>>>(pPre + (size_t)ROWSi * 128 + 64, 128, Wz1, bz1, 64, 64, 0, pT1, 64);
    dense_k<<<2496, 256>>>(pT1, 64, Wz2, bz2, 64, 64, 0, pT2, 64);
    dense_k<<<2496, 256>>>(pT2, 64, Wz3, bz3, 64, 64, 4, pT1, 64);
    dense_k<<<2496, 256>>>(pT1, 64, Wo, bo, 64, 16, 5, (float*)d_out, 16);
}

// round 6
// speedup vs baseline: 2.0953x; 1.0402x over previous
#include <cuda_runtime.h>
#include <cuda_bf16.h>
#include <cstdint>

#define NNi   1024
#define BBi   8
#define TTi   40
#define DINi  16
#define ROWSi 8192
#define DT_SUB 0.025f

typedef __nv_bfloat16 bf16;

// ------------------- static scratch (no runtime allocation) -------------------
__device__ float g_A2 [(size_t)BBi*NNi*NNi];
__device__ float g_X  [(size_t)BBi*TTi*NNi*DINi];
__device__ float g_obs[(size_t)BBi*TTi*NNi];
__device__ float g_AX1[(size_t)BBi*TTi*NNi*DINi];
__device__ float g_AX2[(size_t)BBi*TTi*NNi*DINi];
__device__ float g_S  [(size_t)ROWSi*128];
__device__ float g_u  [(size_t)ROWSi*128];
__device__ float g_pre[(size_t)TTi*ROWSi*128];
__device__ float g_T1 [(size_t)39*ROWSi*64];
__device__ float g_T2 [(size_t)39*ROWSi*64];
// bf16 split operand twins
__device__ bf16 g_Ahi  [(size_t)BBi*NNi*NNi];
__device__ bf16 g_Alo  [(size_t)BBi*NNi*NNi];
__device__ bf16 g_A2hi [(size_t)BBi*NNi*NNi];
__device__ bf16 g_A2lo [(size_t)BBi*NNi*NNi];
__device__ bf16 g_Shi  [(size_t)ROWSi*128];
__device__ bf16 g_Slo  [(size_t)ROWSi*128];
__device__ bf16 g_RHhi [(size_t)ROWSi*128];
__device__ bf16 g_RHlo [(size_t)ROWSi*128];
__device__ bf16 g_B1hi [(size_t)ROWSi*128];
__device__ bf16 g_B1lo [(size_t)ROWSi*128];
__device__ bf16 g_B2hi [(size_t)ROWSi*128];
__device__ bf16 g_B2lo [(size_t)ROWSi*128];
__device__ bf16 g_Xhi  [(size_t)BBi*TTi*NNi*DINi];
__device__ bf16 g_Xlo  [(size_t)BBi*TTi*NNi*DINi];
__device__ bf16 g_AX1hi[(size_t)BBi*TTi*NNi*DINi];
__device__ bf16 g_AX1lo[(size_t)BBi*TTi*NNi*DINi];
__device__ bf16 g_AX2hi[(size_t)BBi*TTi*NNi*DINi];
__device__ bf16 g_AX2lo[(size_t)BBi*TTi*NNi*DINi];
__device__ bf16 g_H1hi [(size_t)2*ROWSi*64];   // kept for dh_epi mode 0 (unused path)
__device__ bf16 g_H1lo [(size_t)2*ROWSi*64];
__device__ bf16 g_zero_bf[16];                  // zero-initialized
// padded bf16 weight splits  [z][Kpad*Npad]
__device__ bf16 g_oW0hi  [2*192*64];
__device__ bf16 g_oW0lo  [2*192*64];
__device__ bf16 g_oWouthi[2*64*64];
__device__ bf16 g_oWoutlo[2*64*64];
__device__ bf16 g_gWghi  [2*256*128];
__device__ bf16 g_gWglo  [2*256*128];
__device__ bf16 g_gWchi  [2*256*64];
__device__ bf16 g_gWclo  [2*256*64];

// ------------------- asm helpers (plain sm_80+ features only) -------------------
__device__ __forceinline__ uint32_t smem_u32(const void* p) {
    uint32_t a;
    asm("{ .reg .u64 t; cvta.to.shared.u64 t, %1; cvt.u32.u64 %0, t; }" : "=r"(a) : "l"(p));
    return a;
}
__device__ __forceinline__ void ldm4(uint32_t* r, uint32_t a) {
    asm volatile("ldmatrix.sync.aligned.m8n8.x4.shared.b16 {%0,%1,%2,%3}, [%4];"
        : "=r"(r[0]), "=r"(r[1]), "=r"(r[2]), "=r"(r[3]) : "r"(a));
}
__device__ __forceinline__ void ldm4t(uint32_t* r, uint32_t a) {
    asm volatile("ldmatrix.sync.aligned.m8n8.x4.trans.shared.b16 {%0,%1,%2,%3}, [%4];"
        : "=r"(r[0]), "=r"(r[1]), "=r"(r[2]), "=r"(r[3]) : "r"(a));
}
__device__ __forceinline__ void mma_bf(float* c, const uint32_t* a, uint32_t b0, uint32_t b1) {
    asm volatile("mma.sync.aligned.m16n8k16.row.col.f32.bf16.bf16.f32 "
        "{%0,%1,%2,%3}, {%4,%5,%6,%7}, {%8,%9}, {%0,%1,%2,%3};"
        : "+f"(c[0]), "+f"(c[1]), "+f"(c[2]), "+f"(c[3])
        : "r"(a[0]), "r"(a[1]), "r"(a[2]), "r"(a[3]), "r"(b0), "r"(b1));
}
__device__ __forceinline__ void cpa16(uint32_t sm, const void* gm) {
    asm volatile("cp.async.cg.shared.global [%0], [%1], 16;"
        :: "r"(sm), "l"(__cvta_generic_to_global(gm)));
}
#define CP_COMMIT() asm volatile("cp.async.commit_group;" ::: "memory")
#define CP_WAIT0()  asm volatile("cp.async.wait_group 0;" ::: "memory")
#define CP_WAIT1()  asm volatile("cp.async.wait_group 1;" ::: "memory")

__device__ __forceinline__ void split_bf(float v, bf16& h, bf16& l) {
    h = __float2bfloat16_rn(v);
    l = __float2bfloat16_rn(v - __bfloat162float(h));
}

// ------------------- init / split kernels -------------------
__global__ void initX_k(const float4* __restrict__ v, const float4* __restrict__ m) {
    int i = blockIdx.x * 256 + threadIdx.x;   // [0, 327680)
    float s = 0.f;
#pragma unroll
    for (int q = 0; q < 4; q++) {
        float4 vv = v[i * 4 + q], mm = m[i * 4 + q];
        s += fabsf(mm.x) + fabsf(mm.y) + fabsf(mm.z) + fabsf(mm.w);
        float4 x = make_float4(vv.x * mm.x, vv.y * mm.y, vv.z * mm.z, vv.w * mm.w);
        ((float4*)g_X)[i * 4 + q] = x;
        size_t o = (size_t)i * 16 + q * 4;
        split_bf(x.x, g_Xhi[o + 0], g_Xlo[o + 0]);
        split_bf(x.y, g_Xhi[o + 1], g_Xlo[o + 1]);
        split_bf(x.z, g_Xhi[o + 2], g_Xlo[o + 2]);
        split_bf(x.w, g_Xhi[o + 3], g_Xlo[o + 3]);
    }
    g_obs[i] = (s > 1e-4f) ? 1.f : 0.f;
}
__global__ void initS_k(const float* __restrict__ h0, const float* __restrict__ z0) {
    int i = blockIdx.x * 256 + threadIdx.x;
    int c = i & 127;
    float v = (c < 64) ? h0[c] : z0[c - 64];
    g_S[i] = v;
    split_bf(v, g_Shi[i], g_Slo[i]);
}
__global__ void splitA_k(const float* __restrict__ src, bf16* __restrict__ hi, bf16* __restrict__ lo) {
    size_t i = (size_t)blockIdx.x * 256 + threadIdx.x;
    split_bf(src[i], hi[i], lo[i]);
}
__global__ void splitW_k(const float* __restrict__ src, bf16* __restrict__ hi, bf16* __restrict__ lo,
                         int K, int N, int Npad) {
    int i = blockIdx.x * 256 + threadIdx.x;   // over Kpad*Npad
    int k = i / Npad, n = i - k * Npad;
    float v = (k < K && n < N) ? src[k * N + n] : 0.f;
    split_bf(v, hi[i], lo[i]);
}

// ------------------- HMMA bf16 3-product diffusion GEMM -------------------
#define STAGE_BYTES 37888
#define A_LO_OFF    10240
#define B_OFF       20480
#define B_LO_OFF    8704

__device__ __forceinline__ void hmma_load_stage(
    uint32_t so, int k0, int t, int row0,
    const bf16* __restrict__ Ah, const bf16* __restrict__ Al,
    const bf16* __restrict__ Bh, const bf16* __restrict__ Bl)
{
#pragma unroll
    for (int i = 0; i < 4; i++) {
        int c = t + i * 256;
        int arr = c >> 9, cc = c & 511, row = cc >> 2, seg = cc & 3;
        const bf16* g = (arr ? Al : Ah) + (size_t)(row0 + row) * NNi + k0 + seg * 8;
        cpa16(so + arr * A_LO_OFF + row * 80 + seg * 16, g);
    }
#pragma unroll
    for (int i = 0; i < 4; i++) {
        int c = t + i * 256;
        int arr = c >> 9, cc = c & 511, k = cc >> 4, seg = cc & 15;
        const bf16* g = (arr ? Bl : Bh) + (size_t)(k0 + k) * 128 + seg * 8;
        cpa16(so + B_OFF + arr * B_LO_OFF + k * 272 + seg * 16, g);
    }
    CP_COMMIT();
}

__global__ void __launch_bounds__(256, 2) gemmA_hmma(
    const bf16* __restrict__ Ahi1, const bf16* __restrict__ Alo1,
    const bf16* __restrict__ Ahi2, const bf16* __restrict__ Alo2,
    const bf16* __restrict__ Bhi, const bf16* __restrict__ Blo,
    bf16* __restrict__ O1hi, bf16* __restrict__ O1lo,
    bf16* __restrict__ O2hi, bf16* __restrict__ O2lo)
{
    extern __shared__ char smraw[];
    int bz = blockIdx.z;
    int b = bz & 7, hop = bz >> 3;
    const bf16* Ah = (hop ? Ahi2 : Ahi1) + (size_t)b * NNi * NNi;
    const bf16* Al = (hop ? Alo2 : Alo1) + (size_t)b * NNi * NNi;
    const bf16* Bh = Bhi + (size_t)b * NNi * 128;
    const bf16* Bl = Blo + (size_t)b * NNi * 128;
    bf16* Ohi = (hop ? O2hi : O1hi) + (size_t)b * NNi * 128;
    bf16* Olo = (hop ? O2lo : O1lo) + (size_t)b * NNi * 128;
    int row0 = blockIdx.x * 128;

    int t = threadIdx.x, wid = t >> 5, lane = t & 31;
    int wm = (wid & 3) * 32, wn = (wid >> 2) * 64;
    uint32_t sbase = smem_u32(smraw);

    float acc[2][8][4];
#pragma unroll
    for (int mt = 0; mt < 2; mt++)
#pragma unroll
        for (int nt = 0; nt < 8; nt++)
#pragma unroll
            for (int q = 0; q < 4; q++) acc[mt][nt][q] = 0.f;

    uint32_t lmRow  = lane & 15;
    uint32_t lmColB = (lane >> 4) * 16;

    hmma_load_stage(sbase, 0, t, row0, Ah, Al, Bh, Bl);

    for (int kt = 0; kt < 32; kt++) {
        if (kt < 31)
            hmma_load_stage(sbase + ((kt + 1) & 1) * STAGE_BYTES, (kt + 1) * 32, t, row0, Ah, Al, Bh, Bl);
        if (kt < 31) { CP_WAIT1(); } else { CP_WAIT0(); }
        __syncthreads();

        uint32_t so = sbase + (kt & 1) * STAGE_BYTES;
#pragma unroll
        for (int ks = 0; ks < 2; ks++) {
            uint32_t ah[2][4], al[2][4];
#pragma unroll
            for (int mt = 0; mt < 2; mt++) {
                uint32_t ad = so + (wm + mt * 16 + lmRow) * 80 + ks * 32 + lmColB;
                ldm4(ah[mt], ad);
                ldm4(al[mt], ad + A_LO_OFF);
            }
#pragma unroll
            for (int np = 0; np < 4; np++) {
                uint32_t bd = so + B_OFF + (ks * 16 + lmRow) * 272 + (wn + np * 16) * 2 + lmColB;
                uint32_t bh[4], bl[4];
                ldm4t(bh, bd);
                ldm4t(bl, bd + B_LO_OFF);
#pragma unroll
                for (int mt = 0; mt < 2; mt++) {
                    mma_bf(acc[mt][2 * np],     ah[mt], bh[0], bh[1]);
                    mma_bf(acc[mt][2 * np + 1], ah[mt], bh[2], bh[3]);
                    mma_bf(acc[mt][2 * np],     ah[mt], bl[0], bl[1]);
                    mma_bf(acc[mt][2 * np + 1], ah[mt], bl[2], bl[3]);
                    mma_bf(acc[mt][2 * np],     al[mt], bh[0], bh[1]);
                    mma_bf(acc[mt][2 * np + 1], al[mt], bh[2], bh[3]);
                }
            }
        }
        __syncthreads();
    }

    int gr = lane >> 2, gc = (lane & 3) * 2;
#pragma unroll
    for (int mt = 0; mt < 2; mt++)
#pragma unroll
        for (int nt = 0; nt < 8; nt++) {
            int r = row0 + wm + mt * 16 + gr;
            int c = wn + nt * 8 + gc;
            bf16 h0, l0, h1, l1;
            split_bf(acc[mt][nt][0], h0, l0); split_bf(acc[mt][nt][1], h1, l1);
            *(__nv_bfloat162*)&Ohi[(size_t)r * 128 + c] = __halves2bfloat162(h0, h1);
            *(__nv_bfloat162*)&Olo[(size_t)r * 128 + c] = __halves2bfloat162(l0, l1);
            split_bf(acc[mt][nt][2], h0, l0); split_bf(acc[mt][nt][3], h1, l1);
            *(__nv_bfloat162*)&Ohi[(size_t)(r + 8) * 128 + c] = __halves2bfloat162(h0, h1);
            *(__nv_bfloat162*)&Olo[(size_t)(r + 8) * 128 + c] = __halves2bfloat162(l0, l1);
        }
}

// ------------------- SIMT batched A-GEMM (precompute only) -------------------
__global__ __launch_bounds__(256, 2) void gemmA_k(
    const float* __restrict__ Aop1, const float* __restrict__ Aop2,
    const float* __restrict__ Bsrc, size_t sB, int ldb, int bmode, int C,
    float* __restrict__ O1, float* __restrict__ O2, size_t sO, int ldo, int omode)
{
    int bz = blockIdx.z;
    int b = bz & 7, hop = bz >> 3;
    const float* Ab = (hop ? Aop2 : Aop1) + (size_t)b * NNi * NNi;
    const float* Bb = Bsrc + (size_t)b * sB;
    float* Ob = (hop ? O2 : O1) + (size_t)b * sO;
    int row0 = blockIdx.x * 128, col0 = blockIdx.y * 128;

    __shared__ float As[16][128];
    __shared__ float Bs[16][128];

    int t  = threadIdx.x;
    int tx = t & 15, ty = t >> 4;
    int rA = ty * 4, cB = tx * 4;

    float acc[2][2][4][4];
#pragma unroll
    for (int a = 0; a < 2; a++)
#pragma unroll
        for (int c = 0; c < 2; c++)
#pragma unroll
            for (int i = 0; i < 4; i++)
#pragma unroll
                for (int j = 0; j < 4; j++) acc[a][c][i][j] = 0.f;

    for (int k0 = 0; k0 < NNi; k0 += 16) {
#pragma unroll
        for (int i = 0; i < 2; i++) {
            int f = t + i * 256;
            int row = f >> 2, kq = (f & 3) * 4;
            float4 v = *(const float4*)&Ab[(size_t)(row0 + row) * NNi + k0 + kq];
            As[kq + 0][row] = v.x; As[kq + 1][row] = v.y;
            As[kq + 2][row] = v.z; As[kq + 3][row] = v.w;
        }
#pragma unroll
        for (int i = 0; i < 2; i++) {
            int f = t + i * 256;
            int k = f >> 5, cq = (f & 31) * 4;
            int col = col0 + cq;
            size_t off;
            if (bmode == 1) off = (size_t)(k0 + k) * 16 + (size_t)(col >> 4) * 16384 + (col & 15);
            else            off = (size_t)(k0 + k) * ldb + col;
            *(float4*)&Bs[k][cq] = *(const float4*)&Bb[off];
        }
        __syncthreads();
#pragma unroll
        for (int k = 0; k < 16; k++) {
            float a[2][4], bb[2][4];
            *(float4*)a[0]  = *(const float4*)&As[k][rA];
            *(float4*)a[1]  = *(const float4*)&As[k][rA + 64];
            *(float4*)bb[0] = *(const float4*)&Bs[k][cB];
            *(float4*)bb[1] = *(const float4*)&Bs[k][cB + 64];
#pragma unroll
            for (int rh = 0; rh < 2; rh++)
#pragma unroll
                for (int ch = 0; ch < 2; ch++)
#pragma unroll
                    for (int i = 0; i < 4; i++)
#pragma unroll
                        for (int j = 0; j < 4; j++)
                            acc[rh][ch][i][j] += a[rh][i] * bb[ch][j];
        }
        __syncthreads();
    }
#pragma unroll
    for (int rh = 0; rh < 2; rh++)
#pragma unroll
        for (int i = 0; i < 4; i++) {
            int row = row0 + rA + rh * 64 + i;
#pragma unroll
            for (int ch = 0; ch < 2; ch++) {
                int col = col0 + cB + ch * 64;
                size_t off;
                if (omode == 1) off = (size_t)row * 16 + (size_t)(col >> 4) * 16384 + (col & 15);
                else            off = (size_t)row * ldo + col;
                *(float4*)&Ob[off] = *(float4*)&acc[rh][ch][i][0];
            }
        }
}

// ------------------- shared pieces for dense HMMA kernels -------------------
#define DH_A_STRIDE 80
#define DH_ALO_OFF  10240
#define DH_B_OFF    20480
#define DH_B_STRIDE 144
#define DH_BLO_OFF  4608
#define DH_STAGE    29696

__device__ __forceinline__ void dh_load_stage(
    uint32_t so, int k0, int row0, int z, int t, int col0, int Kdim, int afmt,
    const bf16* __restrict__ Hhi, const bf16* __restrict__ Hlo,
    const bf16* __restrict__ Whi, const bf16* __restrict__ Wlo, int Npad)
{
#pragma unroll
    for (int i = 0; i < 4; i++) {          // A tile: 128 rows x 32 k, hi+lo
        int c = threadIdx.x + i * 256;
        int arr = c >> 9, cc = c & 511;
        int row = cc >> 2, seg = cc & 3;
        int kk = k0 + seg * 8;
        int grow = row0 + row;
        const bf16* src; size_t off;
        if (afmt == 1) {
            const bf16 *hi, *lo; int kloc;
            if (kk < 64)       { hi = g_Shi;  lo = g_Slo;  kloc = kk; }
            else if (kk < 128) { hi = g_B1hi; lo = g_B1lo; kloc = kk - 64; }
            else               { hi = g_B2hi; lo = g_B2lo; kloc = kk - 128; }
            src = arr ? lo : hi;
            off = (size_t)grow * 128 + z * 64 + kloc;
        } else {               // afmt 2
            if (kk >= Kdim) { src = g_zero_bf; off = 0; }
            else {
                int bb = grow >> 10, n = grow & 1023;
                size_t xb = (((size_t)bb * TTi + t) * NNi + n) * 16;
                const bf16 *hi, *lo; size_t o2;
                if (kk < 16)       { hi = g_Xhi;   lo = g_Xlo;   o2 = xb + kk; }
                else if (kk < 80)  { hi = Hhi;     lo = Hlo;     o2 = (size_t)grow * 128 + z * 64 + (kk - 16); }
                else if (kk < 96)  { hi = g_AX1hi; lo = g_AX1lo; o2 = xb + (kk - 80); }
                else if (kk < 160) { hi = g_B1hi;  lo = g_B1lo;  o2 = (size_t)grow * 128 + z * 64 + (kk - 96); }
                else if (kk < 176) { hi = g_AX2hi; lo = g_AX2lo; o2 = xb + (kk - 160); }
                else               { hi = g_B2hi;  lo = g_B2lo;  o2 = (size_t)grow * 128 + z * 64 + (kk - 176); }
                src = arr ? lo : hi; off = o2;
            }
        }
        cpa16(so + arr * DH_ALO_OFF + row * DH_A_STRIDE + seg * 16, src + off);
    }
#pragma unroll
    for (int i = 0; i < 2; i++) {          // B tile: 32 k x 64 cols, hi+lo
        int c = threadIdx.x + i * 256;
        int arr = c >> 8, cc = c & 255;
        int k = cc >> 3, seg = cc & 7;
        const bf16* w = (arr ? Wlo : Whi) + (size_t)(k0 + k) * Npad + col0 + seg * 8;
        cpa16(so + DH_B_OFF + arr * DH_BLO_OFF + k * DH_B_STRIDE + seg * 16, w);
    }
    CP_COMMIT();
}

__device__ __forceinline__ void dh_epi(int mode, int z, int t, int row, int col, float v) {
    if (mode == 2) {
        float g = 1.f / (1.f + expf(-v));
        if (col < 64) {
            size_t ii = (size_t)row * 128 + z * 64 + col;
            float rh = g * g_S[ii];
            split_bf(rh, g_RHhi[ii], g_RHlo[ii]);
        } else {
            g_u[(size_t)row * 128 + z * 64 + (col - 64)] = g;
        }
    } else { // 3
        float cc = tanhf(v);
        size_t ii = (size_t)row * 128 + z * 64 + col;
        float u = g_u[ii], h = g_S[ii];
        float m = g_obs[((size_t)(row >> 10) * TTi + t) * NNi + (row & 1023)];
        float hn = u * h + (1.f - u) * cc;
        float s = h + m * (hn - h);
        g_S[ii] = s;
        split_bf(s, g_Shi[ii], g_Slo[ii]);
    }
}

// ------------------- HMMA GRU dense (gate / candidate) -------------------
__global__ void __launch_bounds__(256, 2) denseH_k(
    int Kdim, int nkt, int mode, int t,
    const bf16* __restrict__ Hhi, const bf16* __restrict__ Hlo,
    const bf16* __restrict__ W0hi, const bf16* __restrict__ W0lo,
    const bf16* __restrict__ W1hi, const bf16* __restrict__ W1lo, int Npad,
    const float* __restrict__ bias0, const float* __restrict__ bias1)
{
    extern __shared__ char smraw[];
    int z = blockIdx.z;
    int row0 = blockIdx.x * 128;
    int col0 = blockIdx.y * 64;
    const bf16* Whi = z ? W1hi : W0hi;
    const bf16* Wlo = z ? W1lo : W0lo;
    const float* bias = z ? bias1 : bias0;

    int tid = threadIdx.x, wid = tid >> 5, lane = tid & 31;
    int wm = (wid & 3) * 32, wn = (wid >> 2) * 32;
    uint32_t sb = smem_u32(smraw);
    uint32_t lmRow = lane & 15, lmColB = (lane >> 4) * 16;

    float acc[2][4][4];
#pragma unroll
    for (int mt = 0; mt < 2; mt++)
#pragma unroll
        for (int nt = 0; nt < 4; nt++)
#pragma unroll
            for (int q = 0; q < 4; q++) acc[mt][nt][q] = 0.f;

    dh_load_stage(sb, 0, row0, z, t, col0, Kdim, 2, Hhi, Hlo, Whi, Wlo, Npad);

    for (int kt = 0; kt < nkt; kt++) {
        if (kt + 1 < nkt)
            dh_load_stage(sb + ((kt + 1) & 1) * DH_STAGE, (kt + 1) * 32, row0, z, t, col0,
                          Kdim, 2, Hhi, Hlo, Whi, Wlo, Npad);
        if (kt + 1 < nkt) { CP_WAIT1(); } else { CP_WAIT0(); }
        __syncthreads();

        uint32_t so = sb + (kt & 1) * DH_STAGE;
#pragma unroll
        for (int ks = 0; ks < 2; ks++) {
            uint32_t ah[2][4], al[2][4];
#pragma unroll
            for (int mt = 0; mt < 2; mt++) {
                uint32_t ad = so + (wm + mt * 16 + lmRow) * DH_A_STRIDE + ks * 32 + lmColB;
                ldm4(ah[mt], ad);
                ldm4(al[mt], ad + DH_ALO_OFF);
            }
#pragma unroll
            for (int np = 0; np < 2; np++) {
                uint32_t bd = so + DH_B_OFF + (ks * 16 + lmRow) * DH_B_STRIDE + (wn + np * 16) * 2 + lmColB;
                uint32_t bh[4], bl[4];
                ldm4t(bh, bd);
                ldm4t(bl, bd + DH_BLO_OFF);
#pragma unroll
                for (int mt = 0; mt < 2; mt++) {
                    mma_bf(acc[mt][2 * np],     ah[mt], bh[0], bh[1]);
                    mma_bf(acc[mt][2 * np + 1], ah[mt], bh[2], bh[3]);
                    mma_bf(acc[mt][2 * np],     ah[mt], bl[0], bl[1]);
                    mma_bf(acc[mt][2 * np + 1], ah[mt], bl[2], bl[3]);
                    mma_bf(acc[mt][2 * np],     al[mt], bh[0], bh[1]);
                    mma_bf(acc[mt][2 * np + 1], al[mt], bh[2], bh[3]);
                }
            }
        }
        __syncthreads();
    }

    int gr = lane >> 2, gc = (lane & 3) * 2;
#pragma unroll
    for (int mt = 0; mt < 2; mt++)
#pragma unroll
        for (int nt = 0; nt < 4; nt++) {
            int r = row0 + wm + mt * 16 + gr;
            int c = col0 + wn + nt * 8 + gc;
            dh_epi(mode, z, t, r,     c,     acc[mt][nt][0] + bias[c]);
            dh_epi(mode, z, t, r,     c + 1, acc[mt][nt][1] + bias[c + 1]);
            dh_epi(mode, z, t, r + 8, c,     acc[mt][nt][2] + bias[c]);
            dh_epi(mode, z, t, r + 8, c + 1, acc[mt][nt][3] + bias[c + 1]);
        }
}

// ------------------- fused ODE step: tanh(feat@W0) @ Wout -> Euler update -------------------
// grid (64,1,2), 256 thr. smem: 2 stages | H1 hi/lo (128x144B) | Wout hi/lo (64x144B)
#define ODE_H1HI  59392
#define ODE_H1LO  77824
#define ODE_WHI   96256
#define ODE_WLO   105472
#define ODE_SMEM  114688

__global__ void __launch_bounds__(256) denseODE_k(
    int t_pre,
    const bf16* __restrict__ W0hi, const bf16* __restrict__ W0lo,     // [2][192*64]
    const bf16* __restrict__ Wouthi, const bf16* __restrict__ Woutlo, // [2][64*64]
    const float* __restrict__ b0_0, const float* __restrict__ b0_1,
    const float* __restrict__ bo_0, const float* __restrict__ bo_1)
{
    extern __shared__ char smraw[];
    int z = blockIdx.z;
    int row0 = blockIdx.x * 128;
    const bf16* Whi = W0hi + (size_t)z * 12288;
    const bf16* Wlo = W0lo + (size_t)z * 12288;
    const bf16* WoH = Wouthi + (size_t)z * 4096;
    const bf16* WoL = Woutlo + (size_t)z * 4096;
    const float* b0 = z ? b0_1 : b0_0;
    const float* bo = z ? bo_1 : bo_0;

    int tid = threadIdx.x, wid = tid >> 5, lane = tid & 31;
    int wm = (wid & 3) * 32, wn = (wid >> 2) * 32;
    uint32_t sb = smem_u32(smraw);
    uint32_t lmRow = lane & 15, lmColB = (lane >> 4) * 16;

    // stage Wout into smem (plain copies; synced by the loop's barriers)
#pragma unroll
    for (int i = 0; i < 4; i++) {
        int c = tid + i * 256;                // [0,1024): 2 arrays x 512 chunks
        int arr = c >> 9, cc = c & 511, k = cc >> 3, seg = cc & 7;
        const bf16* src = (arr ? WoL : WoH) + (size_t)k * 64 + seg * 8;
        *(uint4*)(smraw + (arr ? ODE_WLO : ODE_WHI) + k * 144 + seg * 16) = *(const uint4*)src;
    }

    float acc[2][4][4];
#pragma unroll
    for (int mt = 0; mt < 2; mt++)
#pragma unroll
        for (int nt = 0; nt < 4; nt++)
#pragma unroll
            for (int q = 0; q < 4; q++) acc[mt][nt][q] = 0.f;

    // ---- stage 1: feat[128x192] @ W0 -> tanh -> smem (bf16 hi/lo) ----
    dh_load_stage(sb, 0, row0, z, 0, 0, 192, 1, nullptr, nullptr, Whi, Wlo, 64);
    for (int kt = 0; kt < 6; kt++) {
        if (kt < 5)
            dh_load_stage(sb + ((kt + 1) & 1) * DH_STAGE, (kt + 1) * 32, row0, z, 0, 0,
                          192, 1, nullptr, nullptr, Whi, Wlo, 64);
        if (kt < 5) { CP_WAIT1(); } else { CP_WAIT0(); }
        __syncthreads();
        uint32_t so = sb + (kt & 1) * DH_STAGE;
#pragma unroll
        for (int ks = 0; ks < 2; ks++) {
            uint32_t ah[2][4], al[2][4];
#pragma unroll
            for (int mt = 0; mt < 2; mt++) {
                uint32_t ad = so + (wm + mt * 16 + lmRow) * DH_A_STRIDE + ks * 32 + lmColB;
                ldm4(ah[mt], ad);
                ldm4(al[mt], ad + DH_ALO_OFF);
            }
#pragma unroll
            for (int np = 0; np < 2; np++) {
                uint32_t bd = so + DH_B_OFF + (ks * 16 + lmRow) * DH_B_STRIDE + (wn + np * 16) * 2 + lmColB;
                uint32_t bh[4], bl[4];
                ldm4t(bh, bd);
                ldm4t(bl, bd + DH_BLO_OFF);
#pragma unroll
                for (int mt = 0; mt < 2; mt++) {
                    mma_bf(acc[mt][2 * np],     ah[mt], bh[0], bh[1]);
                    mma_bf(acc[mt][2 * np + 1], ah[mt], bh[2], bh[3]);
                    mma_bf(acc[mt][2 * np],     ah[mt], bl[0], bl[1]);
                    mma_bf(acc[mt][2 * np + 1], ah[mt], bl[2], bl[3]);
                    mma_bf(acc[mt][2 * np],     al[mt], bh[0], bh[1]);
                    mma_bf(acc[mt][2 * np + 1], al[mt], bh[2], bh[3]);
                }
            }
        }
        __syncthreads();
    }

    int gr = lane >> 2, gc = (lane & 3) * 2;
#pragma unroll
    for (int mt = 0; mt < 2; mt++)
#pragma unroll
        for (int nt = 0; nt < 4; nt++) {
            int rl = wm + mt * 16 + gr;
            int c = wn + nt * 8 + gc;
            float v0 = tanhf(acc[mt][nt][0] + b0[c]);
            float v1 = tanhf(acc[mt][nt][1] + b0[c + 1]);
            float v2 = tanhf(acc[mt][nt][2] + b0[c]);
            float v3 = tanhf(acc[mt][nt][3] + b0[c + 1]);
            bf16 h0, l0, h1, l1;
            split_bf(v0, h0, l0); split_bf(v1, h1, l1);
            *(__nv_bfloat162*)(smraw + ODE_H1HI + rl * 144 + c * 2) = __halves2bfloat162(h0, h1);
            *(__nv_bfloat162*)(smraw + ODE_H1LO + rl * 144 + c * 2) = __halves2bfloat162(l0, l1);
            split_bf(v2, h0, l0); split_bf(v3, h1, l1);
            *(__nv_bfloat162*)(smraw + ODE_H1HI + (rl + 8) * 144 + c * 2) = __halves2bfloat162(h0, h1);
            *(__nv_bfloat162*)(smraw + ODE_H1LO + (rl + 8) * 144 + c * 2) = __halves2bfloat162(l0, l1);
        }
    __syncthreads();

    // ---- stage 2: H1[128x64] @ Wout -> Euler ----
#pragma unroll
    for (int mt = 0; mt < 2; mt++)
#pragma unroll
        for (int nt = 0; nt < 4; nt++)
#pragma unroll
            for (int q = 0; q < 4; q++) acc[mt][nt][q] = 0.f;

#pragma unroll
    for (int ks = 0; ks < 4; ks++) {
        uint32_t ah[2][4], al[2][4];
#pragma unroll
        for (int mt = 0; mt < 2; mt++) {
            uint32_t ad = sb + ODE_H1HI + (wm + mt * 16 + lmRow) * 144 + ks * 32 + lmColB;
            ldm4(ah[mt], ad);
            ldm4(al[mt], ad + (ODE_H1LO - ODE_H1HI));
        }
#pragma unroll
        for (int np = 0; np < 2; np++) {
            uint32_t bd = sb + ODE_WHI + (ks * 16 + lmRow) * 144 + (wn + np * 16) * 2 + lmColB;
            uint32_t bh[4], bl[4];
            ldm4t(bh, bd);
            ldm4t(bl, bd + (ODE_WLO - ODE_WHI));
#pragma unroll
            for (int mt = 0; mt < 2; mt++) {
                mma_bf(acc[mt][2 * np],     ah[mt], bh[0], bh[1]);
                mma_bf(acc[mt][2 * np + 1], ah[mt], bh[2], bh[3]);
                mma_bf(acc[mt][2 * np],     ah[mt], bl[0], bl[1]);
                mma_bf(acc[mt][2 * np + 1], ah[mt], bl[2], bl[3]);
                mma_bf(acc[mt][2 * np],     al[mt], bh[0], bh[1]);
                mma_bf(acc[mt][2 * np + 1], al[mt], bh[2], bh[3]);
            }
        }
    }

#pragma unroll
    for (int mt = 0; mt < 2; mt++)
#pragma unroll
        for (int nt = 0; nt < 4; nt++) {
            int r = row0 + wm + mt * 16 + gr;
            int c = wn + nt * 8 + gc;
#pragma unroll
            for (int q = 0; q < 4; q++) {
                int rr = r + (q >> 1) * 8;
                int cc = c + (q & 1);
                size_t ii = (size_t)rr * 128 + z * 64 + cc;
                float s = g_S[ii] + DT_SUB * tanhf(acc[mt][nt][q] + bo[cc]);
                g_S[ii] = s;
                split_bf(s, g_Shi[ii], g_Slo[ii]);
                if (t_pre >= 0) g_pre[(size_t)t_pre * ((size_t)ROWSi * 128) + ii] = s;
            }
        }
}

// ------------------- SIMT dense (output head only) -------------------
__global__ __launch_bounds__(256, 2) void dense_k(
    const float* __restrict__ Ain, int lda,
    const float* __restrict__ W, const float* __restrict__ bias,
    int Kdim, int Nout, int mode,
    float* __restrict__ Out, int ldo)
{
    int row0 = blockIdx.x * 128, col0 = 0;

    __shared__ float As[16][128];
    __shared__ float Bs[16][64];

    int tt = threadIdx.x;
    int tx = tt & 15, ty = tt >> 4;
    int rA = ty * 4, cBl = tx * 4;

    float acc[2][4][4];
#pragma unroll
    for (int a = 0; a < 2; a++)
#pragma unroll
        for (int i = 0; i < 4; i++)
#pragma unroll
            for (int j = 0; j < 4; j++) acc[a][i][j] = 0.f;

    for (int k0 = 0; k0 < Kdim; k0 += 16) {
#pragma unroll
        for (int i = 0; i < 2; i++) {
            int f = tt + i * 256;
            int row = f >> 2, kq = (f & 3) * 4;
            float4 v = *(const float4*)&Ain[(size_t)(row0 + row) * lda + k0 + kq];
            As[kq + 0][row] = v.x; As[kq + 1][row] = v.y;
            As[kq + 2][row] = v.z; As[kq + 3][row] = v.w;
        }
        {
            int k = tt >> 4, cq = (tt & 15) * 4;
            int col = col0 + cq;
            float4 v = make_float4(0.f, 0.f, 0.f, 0.f);
            if (col < Nout) v = *(const float4*)&W[(size_t)(k0 + k) * Nout + col];
            *(float4*)&Bs[k][cq] = v;
        }
        __syncthreads();
#pragma unroll
        for (int k = 0; k < 16; k++) {
            float a0[4], a1[4], bv[4];
            *(float4*)a0 = *(const float4*)&As[k][rA];
            *(float4*)a1 = *(const float4*)&As[k][rA + 64];
            *(float4*)bv = *(const float4*)&Bs[k][cBl];
#pragma unroll
            for (int i = 0; i < 4; i++)
#pragma unroll
                for (int j = 0; j < 4; j++) {
                    acc[0][i][j] += a0[i] * bv[j];
                    acc[1][i][j] += a1[i] * bv[j];
                }
        }
        __syncthreads();
    }

#pragma unroll
    for (int rh = 0; rh < 2; rh++)
#pragma unroll
        for (int i = 0; i < 4; i++) {
            int row = row0 + rA + rh * 64 + i;
#pragma unroll
            for (int j = 0; j < 4; j++) {
                int col = col0 + cBl + j;
                if (col >= Nout) continue;
                float v = acc[rh][i][j] + bias[col];
                if (mode == 0) {
                    Out[(size_t)row * ldo + col] = tanhf(v);
                } else if (mode == 4) {
                    float g = 1.f / (1.f + expf(-v));
                    Out[(size_t)row * 64 + col] =
                        g * g_pre[(size_t)ROWSi * 128 + (size_t)row * 128 + col];
                } else { // 5
                    int tp = row >> 13, bn = row & 8191;
                    int bb = bn >> 10, n = bn & 1023;
                    Out[(((size_t)bb * 39 + tp) * NNi + n) * 16 + col] = v;
                }
            }
        }
}

// ------------------- host orchestration -------------------
extern "C" void kernel_launch(void* const* d_in, const int* in_sizes, int n_in,
                              void* d_out, int out_size) {
    const float* values  = (const float*)d_in[0];
    const float* masks   = (const float*)d_in[1];
    const float* A       = (const float*)d_in[2];
    const float* h0      = (const float*)d_in[3];
    const float* z0      = (const float*)d_in[4];
    const float* gV_Wg   = (const float*)d_in[5];
    const float* gV_bg   = (const float*)d_in[6];
    const float* gV_Wc   = (const float*)d_in[7];
    const float* gV_bc   = (const float*)d_in[8];
    const float* gG_Wg   = (const float*)d_in[9];
    const float* gG_bg   = (const float*)d_in[10];
    const float* gG_Wc   = (const float*)d_in[11];
    const float* gG_bc   = (const float*)d_in[12];
    const float* oV_W0   = (const float*)d_in[13];
    const float* oV_b0   = (const float*)d_in[14];
    const float* oV_Wout = (const float*)d_in[15];
    const float* oV_bout = (const float*)d_in[16];
    const float* oG_W0   = (const float*)d_in[17];
    const float* oG_b0   = (const float*)d_in[18];
    const float* oG_Wout = (const float*)d_in[19];
    const float* oG_bout = (const float*)d_in[20];
    const float* Wz1     = (const float*)d_in[21];
    const float* bz1     = (const float*)d_in[22];
    const float* Wz2     = (const float*)d_in[23];
    const float* bz2     = (const float*)d_in[24];
    const float* Wz3     = (const float*)d_in[25];
    const float* bz3     = (const float*)d_in[26];
    const float* Wo      = (const float*)d_in[27];
    const float* bo      = (const float*)d_in[28];

    float *pA2, *pX, *pAX1, *pAX2, *pT1, *pT2, *pPre;
    bf16 *pAhi, *pAlo, *pA2hi, *pA2lo, *pShi, *pSlo, *pRHhi, *pRHlo;
    bf16 *pB1hi, *pB1lo, *pB2hi, *pB2lo;
    bf16 *pAX1hi, *pAX1lo, *pAX2hi, *pAX2lo;
    bf16 *pOW0hi, *pOW0lo, *pOWouthi, *pOWoutlo, *pGWghi, *pGWglo, *pGWchi, *pGWclo;
    cudaGetSymbolAddress((void**)&pA2,   g_A2);
    cudaGetSymbolAddress((void**)&pX,    g_X);
    cudaGetSymbolAddress((void**)&pAX1,  g_AX1);
    cudaGetSymbolAddress((void**)&pAX2,  g_AX2);
    cudaGetSymbolAddress((void**)&pT1,   g_T1);
    cudaGetSymbolAddress((void**)&pT2,   g_T2);
    cudaGetSymbolAddress((void**)&pPre,  g_pre);
    cudaGetSymbolAddress((void**)&pAhi,  g_Ahi);
    cudaGetSymbolAddress((void**)&pAlo,  g_Alo);
    cudaGetSymbolAddress((void**)&pA2hi, g_A2hi);
    cudaGetSymbolAddress((void**)&pA2lo, g_A2lo);
    cudaGetSymbolAddress((void**)&pShi,  g_Shi);
    cudaGetSymbolAddress((void**)&pSlo,  g_Slo);
    cudaGetSymbolAddress((void**)&pRHhi, g_RHhi);
    cudaGetSymbolAddress((void**)&pRHlo, g_RHlo);
    cudaGetSymbolAddress((void**)&pB1hi, g_B1hi);
    cudaGetSymbolAddress((void**)&pB1lo, g_B1lo);
    cudaGetSymbolAddress((void**)&pB2hi, g_B2hi);
    cudaGetSymbolAddress((void**)&pB2lo, g_B2lo);
    cudaGetSymbolAddress((void**)&pAX1hi, g_AX1hi);
    cudaGetSymbolAddress((void**)&pAX1lo, g_AX1lo);
    cudaGetSymbolAddress((void**)&pAX2hi, g_AX2hi);
    cudaGetSymbolAddress((void**)&pAX2lo, g_AX2lo);
    cudaGetSymbolAddress((void**)&pOW0hi,   g_oW0hi);
    cudaGetSymbolAddress((void**)&pOW0lo,   g_oW0lo);
    cudaGetSymbolAddress((void**)&pOWouthi, g_oWouthi);
    cudaGetSymbolAddress((void**)&pOWoutlo, g_oWoutlo);
    cudaGetSymbolAddress((void**)&pGWghi,   g_gWghi);
    cudaGetSymbolAddress((void**)&pGWglo,   g_gWglo);
    cudaGetSymbolAddress((void**)&pGWchi,   g_gWchi);
    cudaGetSymbolAddress((void**)&pGWclo,   g_gWclo);

    const size_t sA = (size_t)NNi * NNi;
    const size_t sX = (size_t)TTi * NNi * DINi;
    const int HMMA_SMEM = 2 * STAGE_BYTES;   // 75776
    const int DH_SMEM   = 2 * DH_STAGE;      // 59392
    cudaFuncSetAttribute(gemmA_hmma, cudaFuncAttributeMaxDynamicSharedMemorySize, HMMA_SMEM);
    cudaFuncSetAttribute(denseH_k,   cudaFuncAttributeMaxDynamicSharedMemorySize, DH_SMEM);
    cudaFuncSetAttribute(denseODE_k, cudaFuncAttributeMaxDynamicSharedMemorySize, ODE_SMEM);

    dim3 mmaG(8, 1, 16);

    // Launch order tuned so ncu (-s 5 -c 1) profiles the FIRST gemmA_hmma:
    initX_k<<<1280, 256>>>((const float4*)values, (const float4*)masks);            // 0
    initS_k<<<4096, 256>>>(h0, z0);                                                 // 1
    gemmA_k<<<dim3(8, 8, 8), 256>>>(A, A, A, sA, NNi, 0, 1024, pA2, pA2, sA, NNi, 0); // 2
    splitA_k<<<32768, 256>>>(A,   pAhi,  pAlo);                                     // 3
    splitA_k<<<32768, 256>>>(pA2, pA2hi, pA2lo);                                    // 4
    gemmA_hmma<<<mmaG, 256, HMMA_SMEM>>>(pAhi, pAlo, pA2hi, pA2lo, pShi, pSlo,      // 5 (profiled)
                                         pB1hi, pB1lo, pB2hi, pB2lo);
    // Remaining precompute (needed before the first denseODE / gate):
    gemmA_k<<<dim3(8, 5, 16), 256>>>(A, pA2, pX, sX, 0, 1, 640, pAX1, pAX2, sX, 0, 1);
    splitA_k<<<20480, 256>>>(pAX1, pAX1hi, pAX1lo);
    splitA_k<<<20480, 256>>>(pAX2, pAX2hi, pAX2lo);
    splitW_k<<<48, 256>>>(oV_W0,   pOW0hi,           pOW0lo,           192, 64, 64);
    splitW_k<<<48, 256>>>(oG_W0,   pOW0hi + 12288,   pOW0lo + 12288,   192, 64, 64);
    splitW_k<<<16, 256>>>(oV_Wout, pOWouthi,         pOWoutlo,         64, 64, 64);
    splitW_k<<<16, 256>>>(oG_Wout, pOWouthi + 4096,  pOWoutlo + 4096,  64, 64, 64);
    splitW_k<<<128, 256>>>(gV_Wg,  pGWghi,           pGWglo,           240, 128, 128);
    splitW_k<<<128, 256>>>(gG_Wg,  pGWghi + 32768,   pGWglo + 32768,   240, 128, 128);
    splitW_k<<<64, 256>>>(gV_Wc,   pGWchi,           pGWclo,           240, 64, 64);
    splitW_k<<<64, 256>>>(gG_Wc,   pGWchi + 16384,   pGWclo + 16384,   240, 64, 64);

    for (int t = 0; t < TTi; t++) {
        for (int sub = 0; sub < 2; sub++) {
            if (t || sub)   // the (t=0,sub=0) diffusion GEMM was hoisted above
                gemmA_hmma<<<mmaG, 256, HMMA_SMEM>>>(pAhi, pAlo, pA2hi, pA2lo, pShi, pSlo,
                                                     pB1hi, pB1lo, pB2hi, pB2lo);
            denseODE_k<<<dim3(64, 1, 2), 256, ODE_SMEM>>>((sub == 1) ? t : -1,
                pOW0hi, pOW0lo, pOWouthi, pOWoutlo, oV_b0, oG_b0, oV_bout, oG_bout);
        }
        if (t < TTi - 1) {   // last step's GRU outputs are never read
            gemmA_hmma<<<mmaG, 256, HMMA_SMEM>>>(pAhi, pAlo, pA2hi, pA2lo, pShi, pSlo,
                                                 pB1hi, pB1lo, pB2hi, pB2lo);
            denseH_k<<<dim3(64, 2, 2), 256, DH_SMEM>>>(240, 8, 2, t,
                pShi, pSlo, pGWghi, pGWglo, pGWghi + 32768, pGWglo + 32768, 128,
                gV_bg, gG_bg);
            gemmA_hmma<<<mmaG, 256, HMMA_SMEM>>>(pAhi, pAlo, pA2hi, pA2lo, pRHhi, pRHlo,
                                                 pB1hi, pB1lo, pB2hi, pB2lo);
            denseH_k<<<dim3(64, 1, 2), 256, DH_SMEM>>>(240, 8, 3, t,
                pRHhi, pRHlo, pGWchi, pGWclo, pGWchi + 16384, pGWclo + 16384, 64,
                gV_bc, gG_bc);
        }
    }

    // Output head over t = 1..39 (SIMT)
    dense_k<<<2496, 256>>>(pPre + (size_t)ROWSi * 128 + 64, 128, Wz1, bz1, 64, 64, 0, pT1, 64);
    dense_k<<<2496, 256>>>(pT1, 64, Wz2, bz2, 64, 64, 0, pT2, 64);
    dense_k<<<2496, 256>>>(pT2, 64, Wz3, bz3, 64, 64, 4, pT1, 64);
    dense_k<<<2496, 256>>>(pT1, 64, Wo, bo, 64, 16, 5, (float*)d_out, 16);
}

// round 7
// speedup vs baseline: 2.2037x; 1.0517x over previous
#include <cuda_runtime.h>
#include <cuda_bf16.h>
#include <cstdint>

#define NNi   1024
#define BBi   8
#define TTi   40
#define DINi  16
#define ROWSi 8192
#define DT_SUB 0.025f

typedef __nv_bfloat16 bf16;

// ------------------- static scratch (no runtime allocation) -------------------
__device__ float g_obs[(size_t)BBi*TTi*NNi];
__device__ float g_S  [(size_t)ROWSi*128];
__device__ float g_u  [(size_t)ROWSi*128];
__device__ float g_pre[(size_t)TTi*ROWSi*128];
// bf16 split operand twins
__device__ bf16 g_Ahi  [(size_t)BBi*NNi*NNi];
__device__ bf16 g_Alo  [(size_t)BBi*NNi*NNi];
__device__ bf16 g_A2hi [(size_t)BBi*NNi*NNi];
__device__ bf16 g_A2lo [(size_t)BBi*NNi*NNi];
__device__ bf16 g_Shi  [(size_t)ROWSi*128];
__device__ bf16 g_Slo  [(size_t)ROWSi*128];
__device__ bf16 g_RHhi [(size_t)ROWSi*128];
__device__ bf16 g_RHlo [(size_t)ROWSi*128];
__device__ bf16 g_B1hi [(size_t)ROWSi*128];
__device__ bf16 g_B1lo [(size_t)ROWSi*128];
__device__ bf16 g_B2hi [(size_t)ROWSi*128];
__device__ bf16 g_B2lo [(size_t)ROWSi*128];
__device__ bf16 g_Xhi  [(size_t)BBi*TTi*NNi*DINi];
__device__ bf16 g_Xlo  [(size_t)BBi*TTi*NNi*DINi];
__device__ bf16 g_AX1hi[(size_t)BBi*TTi*NNi*DINi];
__device__ bf16 g_AX1lo[(size_t)BBi*TTi*NNi*DINi];
__device__ bf16 g_AX2hi[(size_t)BBi*TTi*NNi*DINi];
__device__ bf16 g_AX2lo[(size_t)BBi*TTi*NNi*DINi];
__device__ bf16 g_preZhi[(size_t)39*ROWSi*64];
__device__ bf16 g_preZlo[(size_t)39*ROWSi*64];
__device__ bf16 g_T1hi [(size_t)39*ROWSi*64];
__device__ bf16 g_T1lo [(size_t)39*ROWSi*64];
__device__ bf16 g_T2hi [(size_t)39*ROWSi*64];
__device__ bf16 g_T2lo [(size_t)39*ROWSi*64];
__device__ bf16 g_zero_bf[16];                  // zero-initialized
// padded bf16 weight splits
__device__ bf16 g_oW0hi  [2*192*64];
__device__ bf16 g_oW0lo  [2*192*64];
__device__ bf16 g_oWouthi[2*64*64];
__device__ bf16 g_oWoutlo[2*64*64];
__device__ bf16 g_gWghi  [2*256*128];
__device__ bf16 g_gWglo  [2*256*128];
__device__ bf16 g_gWchi  [2*256*64];
__device__ bf16 g_gWclo  [2*256*64];
__device__ bf16 g_hWhi   [4*64*64];             // Wz1,Wz2,Wz3,Wo(pad)
__device__ bf16 g_hWlo   [4*64*64];

// ------------------- asm helpers (plain sm_80+ features only) -------------------
__device__ __forceinline__ uint32_t smem_u32(const void* p) {
    uint32_t a;
    asm("{ .reg .u64 t; cvta.to.shared.u64 t, %1; cvt.u32.u64 %0, t; }" : "=r"(a) : "l"(p));
    return a;
}
__device__ __forceinline__ void ldm4(uint32_t* r, uint32_t a) {
    asm volatile("ldmatrix.sync.aligned.m8n8.x4.shared.b16 {%0,%1,%2,%3}, [%4];"
        : "=r"(r[0]), "=r"(r[1]), "=r"(r[2]), "=r"(r[3]) : "r"(a));
}
__device__ __forceinline__ void ldm4t(uint32_t* r, uint32_t a) {
    asm volatile("ldmatrix.sync.aligned.m8n8.x4.trans.shared.b16 {%0,%1,%2,%3}, [%4];"
        : "=r"(r[0]), "=r"(r[1]), "=r"(r[2]), "=r"(r[3]) : "r"(a));
}
__device__ __forceinline__ void mma_bf(float* c, const uint32_t* a, uint32_t b0, uint32_t b1) {
    asm volatile("mma.sync.aligned.m16n8k16.row.col.f32.bf16.bf16.f32 "
        "{%0,%1,%2,%3}, {%4,%5,%6,%7}, {%8,%9}, {%0,%1,%2,%3};"
        : "+f"(c[0]), "+f"(c[1]), "+f"(c[2]), "+f"(c[3])
        : "r"(a[0]), "r"(a[1]), "r"(a[2]), "r"(a[3]), "r"(b0), "r"(b1));
}
__device__ __forceinline__ void cpa16(uint32_t sm, const void* gm) {
    asm volatile("cp.async.cg.shared.global [%0], [%1], 16;"
        :: "r"(sm), "l"(__cvta_generic_to_global(gm)));
}
#define CP_COMMIT() asm volatile("cp.async.commit_group;" ::: "memory")
#define CP_WAIT0()  asm volatile("cp.async.wait_group 0;" ::: "memory")
#define CP_WAIT1()  asm volatile("cp.async.wait_group 1;" ::: "memory")

__device__ __forceinline__ void split_bf(float v, bf16& h, bf16& l) {
    h = __float2bfloat16_rn(v);
    l = __float2bfloat16_rn(v - __bfloat162float(h));
}

// ------------------- init / split kernels -------------------
__global__ void initX_k(const float4* __restrict__ v, const float4* __restrict__ m) {
    int i = blockIdx.x * 256 + threadIdx.x;   // [0, 327680)
    float s = 0.f;
#pragma unroll
    for (int q = 0; q < 4; q++) {
        float4 vv = v[i * 4 + q], mm = m[i * 4 + q];
        s += fabsf(mm.x) + fabsf(mm.y) + fabsf(mm.z) + fabsf(mm.w);
        float4 x = make_float4(vv.x * mm.x, vv.y * mm.y, vv.z * mm.z, vv.w * mm.w);
        size_t o = (size_t)i * 16 + q * 4;
        split_bf(x.x, g_Xhi[o + 0], g_Xlo[o + 0]);
        split_bf(x.y, g_Xhi[o + 1], g_Xlo[o + 1]);
        split_bf(x.z, g_Xhi[o + 2], g_Xlo[o + 2]);
        split_bf(x.w, g_Xhi[o + 3], g_Xlo[o + 3]);
    }
    g_obs[i] = (s > 1e-4f) ? 1.f : 0.f;
}
__global__ void initS_k(const float* __restrict__ h0, const float* __restrict__ z0) {
    int i = blockIdx.x * 256 + threadIdx.x;
    int c = i & 127;
    float v = (c < 64) ? h0[c] : z0[c - 64];
    g_S[i] = v;
    split_bf(v, g_Shi[i], g_Slo[i]);
}
__global__ void splitA_k(const float* __restrict__ src, bf16* __restrict__ hi, bf16* __restrict__ lo) {
    size_t i = (size_t)blockIdx.x * 256 + threadIdx.x;
    split_bf(src[i], hi[i], lo[i]);
}
__global__ void splitW_k(const float* __restrict__ src, bf16* __restrict__ hi, bf16* __restrict__ lo,
                         int K, int N, int Npad) {
    int i = blockIdx.x * 256 + threadIdx.x;   // over Kpad*Npad
    int k = i / Npad, n = i - k * Npad;
    float v = (k < K && n < N) ? src[k * N + n] : 0.f;
    split_bf(v, hi[i], lo[i]);
}

// ------------------- generalized HMMA bf16 3-product GEMM (K=1024) -------------------
// O[hop][b][M x Ncols] = (hop ? A2 : A)[b] @ B[b]; bxmode/oxmode 1 = X layout.
// 3-stage cp.async pipeline, CTA tile 128x128, 8 warps.
#define GP_STAGE  37888
#define A_LO_OFF  10240
#define B_OFF     20480
#define B_LO_OFF  8704

__device__ __forceinline__ void gp_load(
    uint32_t so, int k0, int row0, int col0, int bT,
    const bf16* __restrict__ Ah, const bf16* __restrict__ Al,
    const bf16* __restrict__ Bh, const bf16* __restrict__ Bl,
    int ldb, int bxmode)
{
    int t = threadIdx.x;
#pragma unroll
    for (int i = 0; i < 4; i++) {              // A: 128 rows x 32 k, hi+lo
        int c = t + i * 256;
        int arr = c >> 9, cc = c & 511, row = cc >> 2, seg = cc & 3;
        const bf16* g = (arr ? Al : Ah) + (size_t)(row0 + row) * NNi + k0 + seg * 8;
        cpa16(so + arr * A_LO_OFF + row * 80 + seg * 16, g);
    }
#pragma unroll
    for (int i = 0; i < 4; i++) {              // B: 32 k x 128 cols, hi+lo
        int c = t + i * 256;
        int arr = c >> 9, cc = c & 511, k = cc >> 4, seg = cc & 15;
        size_t off;
        if (bxmode) {
            int col = col0 + seg * 8;
            off = ((size_t)(bT + (col >> 4)) * NNi + (k0 + k)) * 16 + (col & 15);
        } else {
            off = (size_t)(k0 + k) * ldb + col0 + seg * 8;
        }
        cpa16(so + B_OFF + arr * B_LO_OFF + k * 272 + seg * 16, (arr ? Bl : Bh) + off);
    }
    CP_COMMIT();
}

__global__ void __launch_bounds__(256) gemmP_hmma(
    const bf16* __restrict__ Ahi1, const bf16* __restrict__ Alo1,
    const bf16* __restrict__ Ahi2, const bf16* __restrict__ Alo2,
    const bf16* __restrict__ Bhi, const bf16* __restrict__ Blo,
    int ldb, size_t bstride, int bxmode,
    bf16* __restrict__ O1hi, bf16* __restrict__ O1lo,
    bf16* __restrict__ O2hi, bf16* __restrict__ O2lo,
    int ldo, size_t ostride, int oxmode)
{
    extern __shared__ char smraw[];
    int bz = blockIdx.z;
    int b = bz & 7, hop = bz >> 3;
    const bf16* Ah = (hop ? Ahi2 : Ahi1) + (size_t)b * NNi * NNi;
    const bf16* Al = (hop ? Alo2 : Alo1) + (size_t)b * NNi * NNi;
    const bf16* Bh = bxmode ? Bhi : Bhi + (size_t)b * bstride;
    const bf16* Bl = bxmode ? Blo : Blo + (size_t)b * bstride;
    bf16* Ohi = (hop ? O2hi : O1hi) + (oxmode ? 0 : (size_t)b * ostride);
    bf16* Olo = (hop ? O2lo : O1lo) + (oxmode ? 0 : (size_t)b * ostride);
    int row0 = blockIdx.x * 128, col0 = blockIdx.y * 128;
    int bT = b * TTi;

    int t = threadIdx.x, wid = t >> 5, lane = t & 31;
    int wm = (wid & 3) * 32, wn = (wid >> 2) * 64;
    uint32_t sbase = smem_u32(smraw);

    float acc[2][8][4];
#pragma unroll
    for (int mt = 0; mt < 2; mt++)
#pragma unroll
        for (int nt = 0; nt < 8; nt++)
#pragma unroll
            for (int q = 0; q < 4; q++) acc[mt][nt][q] = 0.f;

    uint32_t lmRow  = lane & 15;
    uint32_t lmColB = (lane >> 4) * 16;

    gp_load(sbase,            0,  row0, col0, bT, Ah, Al, Bh, Bl, ldb, bxmode);
    gp_load(sbase + GP_STAGE, 32, row0, col0, bT, Ah, Al, Bh, Bl, ldb, bxmode);

    int s0 = 0, s1 = 1, s2 = 2;
    for (int kt = 0; kt < 32; kt++) {
        if (kt < 31) { CP_WAIT1(); } else { CP_WAIT0(); }
        __syncthreads();
        if (kt + 2 < 32)
            gp_load(sbase + (uint32_t)s2 * GP_STAGE, (kt + 2) * 32, row0, col0, bT,
                    Ah, Al, Bh, Bl, ldb, bxmode);

        uint32_t so = sbase + (uint32_t)s0 * GP_STAGE;
#pragma unroll
        for (int ks = 0; ks < 2; ks++) {
            uint32_t ah[2][4], al[2][4];
#pragma unroll
            for (int mt = 0; mt < 2; mt++) {
                uint32_t ad = so + (wm + mt * 16 + lmRow) * 80 + ks * 32 + lmColB;
                ldm4(ah[mt], ad);
                ldm4(al[mt], ad + A_LO_OFF);
            }
#pragma unroll
            for (int np = 0; np < 4; np++) {
                uint32_t bd = so + B_OFF + (ks * 16 + lmRow) * 272 + (wn + np * 16) * 2 + lmColB;
                uint32_t bh[4], bl[4];
                ldm4t(bh, bd);
                ldm4t(bl, bd + B_LO_OFF);
#pragma unroll
                for (int mt = 0; mt < 2; mt++) {
                    mma_bf(acc[mt][2 * np],     ah[mt], bh[0], bh[1]);
                    mma_bf(acc[mt][2 * np + 1], ah[mt], bh[2], bh[3]);
                    mma_bf(acc[mt][2 * np],     ah[mt], bl[0], bl[1]);
                    mma_bf(acc[mt][2 * np + 1], ah[mt], bl[2], bl[3]);
                    mma_bf(acc[mt][2 * np],     al[mt], bh[0], bh[1]);
                    mma_bf(acc[mt][2 * np + 1], al[mt], bh[2], bh[3]);
                }
            }
        }
        int sx = s0; s0 = s1; s1 = s2; s2 = sx;
    }

    int gr = lane >> 2, gc = (lane & 3) * 2;
#pragma unroll
    for (int mt = 0; mt < 2; mt++)
#pragma unroll
        for (int nt = 0; nt < 8; nt++) {
            int r = row0 + wm + mt * 16 + gr;
            int c = col0 + wn + nt * 8 + gc;
#pragma unroll
            for (int half = 0; half < 2; half++) {
                int rr = r + half * 8;
                bf16 h0, l0, h1, l1;
                split_bf(acc[mt][nt][half * 2 + 0], h0, l0);
                split_bf(acc[mt][nt][half * 2 + 1], h1, l1);
                size_t off;
                if (oxmode) off = ((size_t)(bT + (c >> 4)) * NNi + rr) * 16 + (c & 15);
                else        off = (size_t)rr * ldo + c;
                *(__nv_bfloat162*)&Ohi[off] = __halves2bfloat162(h0, h1);
                *(__nv_bfloat162*)&Olo[off] = __halves2bfloat162(l0, l1);
            }
        }
}

// ------------------- shared pieces for dense HMMA kernels -------------------
#define DH_A_STRIDE 80
#define DH_ALO_OFF  10240
#define DH_B_OFF    20480
#define DH_B_STRIDE 144
#define DH_BLO_OFF  4608
#define DH_STAGE    29696

__device__ __forceinline__ void dh_load_stage(
    uint32_t so, int k0, int row0, int z, int t, int col0, int Kdim, int afmt,
    const bf16* __restrict__ Hhi, const bf16* __restrict__ Hlo,
    const bf16* __restrict__ Whi, const bf16* __restrict__ Wlo, int Npad)
{
#pragma unroll
    for (int i = 0; i < 4; i++) {          // A tile: 128 rows x 32 k, hi+lo
        int c = threadIdx.x + i * 256;
        int arr = c >> 9, cc = c & 511;
        int row = cc >> 2, seg = cc & 3;
        int kk = k0 + seg * 8;
        int grow = row0 + row;
        const bf16* src; size_t off;
        if (afmt == 3) {                   // generic pair, lda 64
            src = arr ? Hlo : Hhi;
            off = (size_t)grow * 64 + kk;
        } else if (afmt == 1) {
            const bf16 *hi, *lo; int kloc;
            if (kk < 64)       { hi = g_Shi;  lo = g_Slo;  kloc = kk; }
            else if (kk < 128) { hi = g_B1hi; lo = g_B1lo; kloc = kk - 64; }
            else               { hi = g_B2hi; lo = g_B2lo; kloc = kk - 128; }
            src = arr ? lo : hi;
            off = (size_t)grow * 128 + z * 64 + kloc;
        } else {               // afmt 2
            if (kk >= Kdim) { src = g_zero_bf; off = 0; }
            else {
                int bb = grow >> 10, n = grow & 1023;
                size_t xb = (((size_t)bb * TTi + t) * NNi + n) * 16;
                const bf16 *hi, *lo; size_t o2;
                if (kk < 16)       { hi = g_Xhi;   lo = g_Xlo;   o2 = xb + kk; }
                else if (kk < 80)  { hi = Hhi;     lo = Hlo;     o2 = (size_t)grow * 128 + z * 64 + (kk - 16); }
                else if (kk < 96)  { hi = g_AX1hi; lo = g_AX1lo; o2 = xb + (kk - 80); }
                else if (kk < 160) { hi = g_B1hi;  lo = g_B1lo;  o2 = (size_t)grow * 128 + z * 64 + (kk - 96); }
                else if (kk < 176) { hi = g_AX2hi; lo = g_AX2lo; o2 = xb + (kk - 160); }
                else               { hi = g_B2hi;  lo = g_B2lo;  o2 = (size_t)grow * 128 + z * 64 + (kk - 176); }
                src = arr ? lo : hi; off = o2;
            }
        }
        cpa16(so + arr * DH_ALO_OFF + row * DH_A_STRIDE + seg * 16, src + off);
    }
#pragma unroll
    for (int i = 0; i < 2; i++) {          // B tile: 32 k x 64 cols, hi+lo
        int c = threadIdx.x + i * 256;
        int arr = c >> 8, cc = c & 255;
        int k = cc >> 3, seg = cc & 7;
        const bf16* w = (arr ? Wlo : Whi) + (size_t)(k0 + k) * Npad + col0 + seg * 8;
        cpa16(so + DH_B_OFF + arr * DH_BLO_OFF + k * DH_B_STRIDE + seg * 16, w);
    }
    CP_COMMIT();
}

__device__ __forceinline__ void dh_epi(int mode, int z, int t, int row, int col, float v) {
    if (mode == 2) {
        float g = 1.f / (1.f + expf(-v));
        if (col < 64) {
            size_t ii = (size_t)row * 128 + z * 64 + col;
            float rh = g * g_S[ii];
            split_bf(rh, g_RHhi[ii], g_RHlo[ii]);
        } else {
            g_u[(size_t)row * 128 + z * 64 + (col - 64)] = g;
        }
    } else { // 3
        float cc = tanhf(v);
        size_t ii = (size_t)row * 128 + z * 64 + col;
        float u = g_u[ii], h = g_S[ii];
        float m = g_obs[((size_t)(row >> 10) * TTi + t) * NNi + (row & 1023)];
        float hn = u * h + (1.f - u) * cc;
        float s = h + m * (hn - h);
        g_S[ii] = s;
        split_bf(s, g_Shi[ii], g_Slo[ii]);
    }
}

// ------------------- HMMA dense (GRU gate/cand + output head) -------------------
// modes: 2 gate | 3 cand blend | 4 tanh->pair out | 5 sigmoid*hv_pre->pair out | 6 plain->d_out
__global__ void __launch_bounds__(256, 2) denseH_k(
    int afmt, int Kdim, int nkt, int mode, int t,
    const bf16* __restrict__ Hhi, const bf16* __restrict__ Hlo,
    const bf16* __restrict__ W0hi, const bf16* __restrict__ W0lo,
    const bf16* __restrict__ W1hi, const bf16* __restrict__ W1lo, int Npad,
    const float* __restrict__ bias0, const float* __restrict__ bias1,
    bf16* __restrict__ Ohi, bf16* __restrict__ Olo, float* __restrict__ out4)
{
    extern __shared__ char smraw[];
    int z = blockIdx.z;
    int row0 = blockIdx.x * 128;
    int col0 = blockIdx.y * 64;
    const bf16* Whi = z ? W1hi : W0hi;
    const bf16* Wlo = z ? W1lo : W0lo;
    const float* bias = z ? bias1 : bias0;

    int tid = threadIdx.x, wid = tid >> 5, lane = tid & 31;
    int wm = (wid & 3) * 32, wn = (wid >> 2) * 32;
    uint32_t sb = smem_u32(smraw);
    uint32_t lmRow = lane & 15, lmColB = (lane >> 4) * 16;

    float acc[2][4][4];
#pragma unroll
    for (int mt = 0; mt < 2; mt++)
#pragma unroll
        for (int nt = 0; nt < 4; nt++)
#pragma unroll
            for (int q = 0; q < 4; q++) acc[mt][nt][q] = 0.f;

    dh_load_stage(sb, 0, row0, z, t, col0, Kdim, afmt, Hhi, Hlo, Whi, Wlo, Npad);

    for (int kt = 0; kt < nkt; kt++) {
        if (kt + 1 < nkt)
            dh_load_stage(sb + ((kt + 1) & 1) * DH_STAGE, (kt + 1) * 32, row0, z, t, col0,
                          Kdim, afmt, Hhi, Hlo, Whi, Wlo, Npad);
        if (kt + 1 < nkt) { CP_WAIT1(); } else { CP_WAIT0(); }
        __syncthreads();

        uint32_t so = sb + (kt & 1) * DH_STAGE;
#pragma unroll
        for (int ks = 0; ks < 2; ks++) {
            uint32_t ah[2][4], al[2][4];
#pragma unroll
            for (int mt = 0; mt < 2; mt++) {
                uint32_t ad = so + (wm + mt * 16 + lmRow) * DH_A_STRIDE + ks * 32 + lmColB;
                ldm4(ah[mt], ad);
                ldm4(al[mt], ad + DH_ALO_OFF);
            }
#pragma unroll
            for (int np = 0; np < 2; np++) {
                uint32_t bd = so + DH_B_OFF + (ks * 16 + lmRow) * DH_B_STRIDE + (wn + np * 16) * 2 + lmColB;
                uint32_t bh[4], bl[4];
                ldm4t(bh, bd);
                ldm4t(bl, bd + DH_BLO_OFF);
#pragma unroll
                for (int mt = 0; mt < 2; mt++) {
                    mma_bf(acc[mt][2 * np],     ah[mt], bh[0], bh[1]);
                    mma_bf(acc[mt][2 * np + 1], ah[mt], bh[2], bh[3]);
                    mma_bf(acc[mt][2 * np],     ah[mt], bl[0], bl[1]);
                    mma_bf(acc[mt][2 * np + 1], ah[mt], bl[2], bl[3]);
                    mma_bf(acc[mt][2 * np],     al[mt], bh[0], bh[1]);
                    mma_bf(acc[mt][2 * np + 1], al[mt], bh[2], bh[3]);
                }
            }
        }
        __syncthreads();
    }

    int gr = lane >> 2, gc = (lane & 3) * 2;
#pragma unroll
    for (int mt = 0; mt < 2; mt++)
#pragma unroll
        for (int nt = 0; nt < 4; nt++) {
            int r = row0 + wm + mt * 16 + gr;
            int c = col0 + wn + nt * 8 + gc;
            if (mode <= 3) {
                dh_epi(mode, z, t, r,     c,     acc[mt][nt][0] + bias[c]);
                dh_epi(mode, z, t, r,     c + 1, acc[mt][nt][1] + bias[c + 1]);
                dh_epi(mode, z, t, r + 8, c,     acc[mt][nt][2] + bias[c]);
                dh_epi(mode, z, t, r + 8, c + 1, acc[mt][nt][3] + bias[c + 1]);
            } else if (mode == 4) {
#pragma unroll
                for (int half = 0; half < 2; half++) {
                    int rr = r + half * 8;
                    float v0 = tanhf(acc[mt][nt][half * 2 + 0] + bias[c]);
                    float v1 = tanhf(acc[mt][nt][half * 2 + 1] + bias[c + 1]);
                    bf16 h0, l0, h1, l1;
                    split_bf(v0, h0, l0); split_bf(v1, h1, l1);
                    size_t off = (size_t)rr * 64 + c;
                    *(__nv_bfloat162*)&Ohi[off] = __halves2bfloat162(h0, h1);
                    *(__nv_bfloat162*)&Olo[off] = __halves2bfloat162(l0, l1);
                }
            } else if (mode == 5) {
#pragma unroll
                for (int half = 0; half < 2; half++) {
                    int rr = r + half * 8;
                    float g0 = 1.f / (1.f + expf(-(acc[mt][nt][half * 2 + 0] + bias[c])));
                    float g1 = 1.f / (1.f + expf(-(acc[mt][nt][half * 2 + 1] + bias[c + 1])));
                    float v0 = g0 * g_pre[(size_t)(rr + ROWSi) * 128 + c];
                    float v1 = g1 * g_pre[(size_t)(rr + ROWSi) * 128 + c + 1];
                    bf16 h0, l0, h1, l1;
                    split_bf(v0, h0, l0); split_bf(v1, h1, l1);
                    size_t off = (size_t)rr * 64 + c;
                    *(__nv_bfloat162*)&Ohi[off] = __halves2bfloat162(h0, h1);
                    *(__nv_bfloat162*)&Olo[off] = __halves2bfloat162(l0, l1);
                }
            } else { // 6: final output -> d_out remapped [8,39,1024,16]
#pragma unroll
                for (int half = 0; half < 2; half++) {
                    int rr = r + half * 8;
                    int tp = rr >> 13, bn = rr & 8191;
                    int bb = bn >> 10, n = bn & 1023;
                    size_t ob = (((size_t)bb * 39 + tp) * NNi + n) * 16;
                    if (c < 16)     out4[ob + c]     = acc[mt][nt][half * 2 + 0] + bias[c];
                    if (c + 1 < 16) out4[ob + c + 1] = acc[mt][nt][half * 2 + 1] + bias[c + 1];
                }
            }
        }
}

// ------------------- fused ODE step: tanh(feat@W0) @ Wout -> Euler update -------------------
#define ODE_H1HI  59392
#define ODE_H1LO  77824
#define ODE_WHI   96256
#define ODE_WLO   105472
#define ODE_SMEM  114688

__global__ void __launch_bounds__(256) denseODE_k(
    int t_pre,
    const bf16* __restrict__ W0hi, const bf16* __restrict__ W0lo,
    const bf16* __restrict__ Wouthi, const bf16* __restrict__ Woutlo,
    const float* __restrict__ b0_0, const float* __restrict__ b0_1,
    const float* __restrict__ bo_0, const float* __restrict__ bo_1)
{
    extern __shared__ char smraw[];
    int z = blockIdx.z;
    int row0 = blockIdx.x * 128;
    const bf16* Whi = W0hi + (size_t)z * 12288;
    const bf16* Wlo = W0lo + (size_t)z * 12288;
    const bf16* WoH = Wouthi + (size_t)z * 4096;
    const bf16* WoL = Woutlo + (size_t)z * 4096;
    const float* b0 = z ? b0_1 : b0_0;
    const float* bo = z ? bo_1 : bo_0;

    int tid = threadIdx.x, wid = tid >> 5, lane = tid & 31;
    int wm = (wid & 3) * 32, wn = (wid >> 2) * 32;
    uint32_t sb = smem_u32(smraw);
    uint32_t lmRow = lane & 15, lmColB = (lane >> 4) * 16;

#pragma unroll
    for (int i = 0; i < 4; i++) {
        int c = tid + i * 256;
        int arr = c >> 9, cc = c & 511, k = cc >> 3, seg = cc & 7;
        const bf16* src = (arr ? WoL : WoH) + (size_t)k * 64 + seg * 8;
        *(uint4*)(smraw + (arr ? ODE_WLO : ODE_WHI) + k * 144 + seg * 16) = *(const uint4*)src;
    }

    float acc[2][4][4];
#pragma unroll
    for (int mt = 0; mt < 2; mt++)
#pragma unroll
        for (int nt = 0; nt < 4; nt++)
#pragma unroll
            for (int q = 0; q < 4; q++) acc[mt][nt][q] = 0.f;

    dh_load_stage(sb, 0, row0, z, 0, 0, 192, 1, nullptr, nullptr, Whi, Wlo, 64);
    for (int kt = 0; kt < 6; kt++) {
        if (kt < 5)
            dh_load_stage(sb + ((kt + 1) & 1) * DH_STAGE, (kt + 1) * 32, row0, z, 0, 0,
                          192, 1, nullptr, nullptr, Whi, Wlo, 64);
        if (kt < 5) { CP_WAIT1(); } else { CP_WAIT0(); }
        __syncthreads();
        uint32_t so = sb + (kt & 1) * DH_STAGE;
#pragma unroll
        for (int ks = 0; ks < 2; ks++) {
            uint32_t ah[2][4], al[2][4];
#pragma unroll
            for (int mt = 0; mt < 2; mt++) {
                uint32_t ad = so + (wm + mt * 16 + lmRow) * DH_A_STRIDE + ks * 32 + lmColB;
                ldm4(ah[mt], ad);
                ldm4(al[mt], ad + DH_ALO_OFF);
            }
#pragma unroll
            for (int np = 0; np < 2; np++) {
                uint32_t bd = so + DH_B_OFF + (ks * 16 + lmRow) * DH_B_STRIDE + (wn + np * 16) * 2 + lmColB;
                uint32_t bh[4], bl[4];
                ldm4t(bh, bd);
                ldm4t(bl, bd + DH_BLO_OFF);
#pragma unroll
                for (int mt = 0; mt < 2; mt++) {
                    mma_bf(acc[mt][2 * np],     ah[mt], bh[0], bh[1]);
                    mma_bf(acc[mt][2 * np + 1], ah[mt], bh[2], bh[3]);
                    mma_bf(acc[mt][2 * np],     ah[mt], bl[0], bl[1]);
                    mma_bf(acc[mt][2 * np + 1], ah[mt], bl[2], bl[3]);
                    mma_bf(acc[mt][2 * np],     al[mt], bh[0], bh[1]);
                    mma_bf(acc[mt][2 * np + 1], al[mt], bh[2], bh[3]);
                }
            }
        }
        __syncthreads();
    }

    int gr = lane >> 2, gc = (lane & 3) * 2;
#pragma unroll
    for (int mt = 0; mt < 2; mt++)
#pragma unroll
        for (int nt = 0; nt < 4; nt++) {
            int rl = wm + mt * 16 + gr;
            int c = wn + nt * 8 + gc;
            float v0 = tanhf(acc[mt][nt][0] + b0[c]);
            float v1 = tanhf(acc[mt][nt][1] + b0[c + 1]);
            float v2 = tanhf(acc[mt][nt][2] + b0[c]);
            float v3 = tanhf(acc[mt][nt][3] + b0[c + 1]);
            bf16 h0, l0, h1, l1;
            split_bf(v0, h0, l0); split_bf(v1, h1, l1);
            *(__nv_bfloat162*)(smraw + ODE_H1HI + rl * 144 + c * 2) = __halves2bfloat162(h0, h1);
            *(__nv_bfloat162*)(smraw + ODE_H1LO + rl * 144 + c * 2) = __halves2bfloat162(l0, l1);
            split_bf(v2, h0, l0); split_bf(v3, h1, l1);
            *(__nv_bfloat162*)(smraw + ODE_H1HI + (rl + 8) * 144 + c * 2) = __halves2bfloat162(h0, h1);
            *(__nv_bfloat162*)(smraw + ODE_H1LO + (rl + 8) * 144 + c * 2) = __halves2bfloat162(l0, l1);
        }
    __syncthreads();

#pragma unroll
    for (int mt = 0; mt < 2; mt++)
#pragma unroll
        for (int nt = 0; nt < 4; nt++)
#pragma unroll
            for (int q = 0; q < 4; q++) acc[mt][nt][q] = 0.f;

#pragma unroll
    for (int ks = 0; ks < 4; ks++) {
        uint32_t ah[2][4], al[2][4];
#pragma unroll
        for (int mt = 0; mt < 2; mt++) {
            uint32_t ad = sb + ODE_H1HI + (wm + mt * 16 + lmRow) * 144 + ks * 32 + lmColB;
            ldm4(ah[mt], ad);
            ldm4(al[mt], ad + (ODE_H1LO - ODE_H1HI));
        }
#pragma unroll
        for (int np = 0; np < 2; np++) {
            uint32_t bd = sb + ODE_WHI + (ks * 16 + lmRow) * 144 + (wn + np * 16) * 2 + lmColB;
            uint32_t bh[4], bl[4];
            ldm4t(bh, bd);
            ldm4t(bl, bd + (ODE_WLO - ODE_WHI));
#pragma unroll
            for (int mt = 0; mt < 2; mt++) {
                mma_bf(acc[mt][2 * np],     ah[mt], bh[0], bh[1]);
                mma_bf(acc[mt][2 * np + 1], ah[mt], bh[2], bh[3]);
                mma_bf(acc[mt][2 * np],     ah[mt], bl[0], bl[1]);
                mma_bf(acc[mt][2 * np + 1], ah[mt], bl[2], bl[3]);
                mma_bf(acc[mt][2 * np],     al[mt], bh[0], bh[1]);
                mma_bf(acc[mt][2 * np + 1], al[mt], bh[2], bh[3]);
            }
        }
    }

#pragma unroll
    for (int mt = 0; mt < 2; mt++)
#pragma unroll
        for (int nt = 0; nt < 4; nt++) {
            int r = row0 + wm + mt * 16 + gr;
            int c = wn + nt * 8 + gc;
#pragma unroll
            for (int q = 0; q < 4; q++) {
                int rr = r + (q >> 1) * 8;
                int cc = c + (q & 1);
                size_t ii = (size_t)rr * 128 + z * 64 + cc;
                float s = g_S[ii] + DT_SUB * tanhf(acc[mt][nt][q] + bo[cc]);
                g_S[ii] = s;
                split_bf(s, g_Shi[ii], g_Slo[ii]);
                if (t_pre >= 0) {
                    g_pre[(size_t)t_pre * ((size_t)ROWSi * 128) + ii] = s;
                    if (t_pre >= 1 && z == 1) {
                        size_t pz = ((size_t)(t_pre - 1) * ROWSi + rr) * 64 + cc;
                        split_bf(s, g_preZhi[pz], g_preZlo[pz]);
                    }
                }
            }
        }
}

// ------------------- host orchestration -------------------
extern "C" void kernel_launch(void* const* d_in, const int* in_sizes, int n_in,
                              void* d_out, int out_size) {
    const float* values  = (const float*)d_in[0];
    const float* masks   = (const float*)d_in[1];
    const float* A       = (const float*)d_in[2];
    const float* h0      = (const float*)d_in[3];
    const float* z0      = (const float*)d_in[4];
    const float* gV_Wg   = (const float*)d_in[5];
    const float* gV_bg   = (const float*)d_in[6];
    const float* gV_Wc   = (const float*)d_in[7];
    const float* gV_bc   = (const float*)d_in[8];
    const float* gG_Wg   = (const float*)d_in[9];
    const float* gG_bg   = (const float*)d_in[10];
    const float* gG_Wc   = (const float*)d_in[11];
    const float* gG_bc   = (const float*)d_in[12];
    const float* oV_W0   = (const float*)d_in[13];
    const float* oV_b0   = (const float*)d_in[14];
    const float* oV_Wout = (const float*)d_in[15];
    const float* oV_bout = (const float*)d_in[16];
    const float* oG_W0   = (const float*)d_in[17];
    const float* oG_b0   = (const float*)d_in[18];
    const float* oG_Wout = (const float*)d_in[19];
    const float* oG_bout = (const float*)d_in[20];
    const float* Wz1     = (const float*)d_in[21];
    const float* bz1     = (const float*)d_in[22];
    const float* Wz2     = (const float*)d_in[23];
    const float* bz2     = (const float*)d_in[24];
    const float* Wz3     = (const float*)d_in[25];
    const float* bz3     = (const float*)d_in[26];
    const float* Wo      = (const float*)d_in[27];
    const float* bo      = (const float*)d_in[28];

    bf16 *pAhi, *pAlo, *pA2hi, *pA2lo, *pShi, *pSlo, *pRHhi, *pRHlo;
    bf16 *pB1hi, *pB1lo, *pB2hi, *pB2lo;
    bf16 *pXhi, *pXlo, *pAX1hi, *pAX1lo, *pAX2hi, *pAX2lo;
    bf16 *pPZhi, *pPZlo, *pT1hi, *pT1lo, *pT2hi, *pT2lo;
    bf16 *pOW0hi, *pOW0lo, *pOWouthi, *pOWoutlo, *pGWghi, *pGWglo, *pGWchi, *pGWclo;
    bf16 *pHWhi, *pHWlo;
    cudaGetSymbolAddress((void**)&pAhi,  g_Ahi);
    cudaGetSymbolAddress((void**)&pAlo,  g_Alo);
    cudaGetSymbolAddress((void**)&pA2hi, g_A2hi);
    cudaGetSymbolAddress((void**)&pA2lo, g_A2lo);
    cudaGetSymbolAddress((void**)&pShi,  g_Shi);
    cudaGetSymbolAddress((void**)&pSlo,  g_Slo);
    cudaGetSymbolAddress((void**)&pRHhi, g_RHhi);
    cudaGetSymbolAddress((void**)&pRHlo, g_RHlo);
    cudaGetSymbolAddress((void**)&pB1hi, g_B1hi);
    cudaGetSymbolAddress((void**)&pB1lo, g_B1lo);
    cudaGetSymbolAddress((void**)&pB2hi, g_B2hi);
    cudaGetSymbolAddress((void**)&pB2lo, g_B2lo);
    cudaGetSymbolAddress((void**)&pXhi,  g_Xhi);
    cudaGetSymbolAddress((void**)&pXlo,  g_Xlo);
    cudaGetSymbolAddress((void**)&pAX1hi, g_AX1hi);
    cudaGetSymbolAddress((void**)&pAX1lo, g_AX1lo);
    cudaGetSymbolAddress((void**)&pAX2hi, g_AX2hi);
    cudaGetSymbolAddress((void**)&pAX2lo, g_AX2lo);
    cudaGetSymbolAddress((void**)&pPZhi, g_preZhi);
    cudaGetSymbolAddress((void**)&pPZlo, g_preZlo);
    cudaGetSymbolAddress((void**)&pT1hi, g_T1hi);
    cudaGetSymbolAddress((void**)&pT1lo, g_T1lo);
    cudaGetSymbolAddress((void**)&pT2hi, g_T2hi);
    cudaGetSymbolAddress((void**)&pT2lo, g_T2lo);
    cudaGetSymbolAddress((void**)&pOW0hi,   g_oW0hi);
    cudaGetSymbolAddress((void**)&pOW0lo,   g_oW0lo);
    cudaGetSymbolAddress((void**)&pOWouthi, g_oWouthi);
    cudaGetSymbolAddress((void**)&pOWoutlo, g_oWoutlo);
    cudaGetSymbolAddress((void**)&pGWghi,   g_gWghi);
    cudaGetSymbolAddress((void**)&pGWglo,   g_gWglo);
    cudaGetSymbolAddress((void**)&pGWchi,   g_gWchi);
    cudaGetSymbolAddress((void**)&pGWclo,   g_gWclo);
    cudaGetSymbolAddress((void**)&pHWhi,    g_hWhi);
    cudaGetSymbolAddress((void**)&pHWlo,    g_hWlo);

    const int GP3 = 3 * GP_STAGE;            // 113664
    const int DH_SMEM = 2 * DH_STAGE;        // 59392
    cudaFuncSetAttribute(gemmP_hmma, cudaFuncAttributeMaxDynamicSharedMemorySize, GP3);
    cudaFuncSetAttribute(denseH_k,   cudaFuncAttributeMaxDynamicSharedMemorySize, DH_SMEM);
    cudaFuncSetAttribute(denseODE_k, cudaFuncAttributeMaxDynamicSharedMemorySize, ODE_SMEM);

    const size_t sAA = (size_t)NNi * NNi;
    const size_t sS  = (size_t)NNi * 128;

    initX_k<<<1280, 256>>>((const float4*)values, (const float4*)masks);            // 0
    initS_k<<<4096, 256>>>(h0, z0);                                                 // 1
    splitA_k<<<32768, 256>>>(A, pAhi, pAlo);                                        // 2
    // A2 = A @ A  (bf16 3-product; grid.z=8 -> hop=0 path only)                    // 3 (profiled)
    gemmP_hmma<<<dim3(8, 8, 8), 256, GP3>>>(pAhi, pAlo, pAhi, pAlo,
        pAhi, pAlo, NNi, sAA, 0, pA2hi, pA2lo, pA2hi, pA2lo, NNi, sAA, 0);
    // AX1 = A @ X, AX2 = A2 @ X for all 40 steps (640 cols, X layout)
    gemmP_hmma<<<dim3(8, 5, 16), 256, GP3>>>(pAhi, pAlo, pA2hi, pA2lo,
        pXhi, pXlo, 0, 0, 1, pAX1hi, pAX1lo, pAX2hi, pAX2lo, 0, 0, 1);
    // first in-loop diffusion (t=0, sub=0) hoisted
    gemmP_hmma<<<dim3(8, 1, 16), 256, GP3>>>(pAhi, pAlo, pA2hi, pA2lo,
        pShi, pSlo, 128, sS, 0, pB1hi, pB1lo, pB2hi, pB2lo, 128, sS, 0);
    // weight splits
    splitW_k<<<48, 256>>>(oV_W0,   pOW0hi,           pOW0lo,           192, 64, 64);
    splitW_k<<<48, 256>>>(oG_W0,   pOW0hi + 12288,   pOW0lo + 12288,   192, 64, 64);
    splitW_k<<<16, 256>>>(oV_Wout, pOWouthi,         pOWoutlo,         64, 64, 64);
    splitW_k<<<16, 256>>>(oG_Wout, pOWouthi + 4096,  pOWoutlo + 4096,  64, 64, 64);
    splitW_k<<<128, 256>>>(gV_Wg,  pGWghi,           pGWglo,           240, 128, 128);
    splitW_k<<<128, 256>>>(gG_Wg,  pGWghi + 32768,   pGWglo + 32768,   240, 128, 128);
    splitW_k<<<64, 256>>>(gV_Wc,   pGWchi,           pGWclo,           240, 64, 64);
    splitW_k<<<64, 256>>>(gG_Wc,   pGWchi + 16384,   pGWclo + 16384,   240, 64, 64);
    splitW_k<<<16, 256>>>(Wz1, pHWhi,         pHWlo,         64, 64, 64);
    splitW_k<<<16, 256>>>(Wz2, pHWhi + 4096,  pHWlo + 4096,  64, 64, 64);
    splitW_k<<<16, 256>>>(Wz3, pHWhi + 8192,  pHWlo + 8192,  64, 64, 64);
    splitW_k<<<16, 256>>>(Wo,  pHWhi + 12288, pHWlo + 12288, 64, 16, 64);

    dim3 mmaG(8, 1, 16);
    for (int t = 0; t < TTi; t++) {
        for (int sub = 0; sub < 2; sub++) {
            if (t || sub)
                gemmP_hmma<<<mmaG, 256, GP3>>>(pAhi, pAlo, pA2hi, pA2lo,
                    pShi, pSlo, 128, sS, 0, pB1hi, pB1lo, pB2hi, pB2lo, 128, sS, 0);
            denseODE_k<<<dim3(64, 1, 2), 256, ODE_SMEM>>>((sub == 1) ? t : -1,
                pOW0hi, pOW0lo, pOWouthi, pOWoutlo, oV_b0, oG_b0, oV_bout, oG_bout);
        }
        if (t < TTi - 1) {   // last step's GRU outputs are never read
            gemmP_hmma<<<mmaG, 256, GP3>>>(pAhi, pAlo, pA2hi, pA2lo,
                pShi, pSlo, 128, sS, 0, pB1hi, pB1lo, pB2hi, pB2lo, 128, sS, 0);
            denseH_k<<<dim3(64, 2, 2), 256, DH_SMEM>>>(2, 240, 8, 2, t,
                pShi, pSlo, pGWghi, pGWglo, pGWghi + 32768, pGWglo + 32768, 128,
                gV_bg, gG_bg, nullptr, nullptr, nullptr);
            gemmP_hmma<<<mmaG, 256, GP3>>>(pAhi, pAlo, pA2hi, pA2lo,
                pRHhi, pRHlo, 128, sS, 0, pB1hi, pB1lo, pB2hi, pB2lo, 128, sS, 0);
            denseH_k<<<dim3(64, 1, 2), 256, DH_SMEM>>>(2, 240, 8, 3, t,
                pRHhi, pRHlo, pGWchi, pGWclo, pGWchi + 16384, pGWclo + 16384, 64,
                gV_bc, gG_bc, nullptr, nullptr, nullptr);
        }
    }

    // Output head over t = 1..39 (HMMA, rows 319488 = 2496*128)
    denseH_k<<<dim3(2496, 1, 1), 256, DH_SMEM>>>(3, 64, 2, 4, 0,
        pPZhi, pPZlo, pHWhi, pHWlo, pHWhi, pHWlo, 64, bz1, bz1,
        pT1hi, pT1lo, nullptr);
    denseH_k<<<dim3(2496, 1, 1), 256, DH_SMEM>>>(3, 64, 2, 4, 0,
        pT1hi, pT1lo, pHWhi + 4096, pHWlo + 4096, pHWhi + 4096, pHWlo + 4096, 64, bz2, bz2,
        pT2hi, pT2lo, nullptr);
    denseH_k<<<dim3(2496, 1, 1), 256, DH_SMEM>>>(3, 64, 2, 5, 0,
        pT2hi, pT2lo, pHWhi + 8192, pHWlo + 8192, pHWhi + 8192, pHWlo + 8192, 64, bz3, bz3,
        pT1hi, pT1lo, nullptr);
    denseH_k<<<dim3(2496, 1, 1), 256, DH_SMEM>>>(3, 64, 2, 6, 0,
        pT1hi, pT1lo, pHWhi + 12288, pHWlo + 12288, pHWhi + 12288, pHWlo + 12288, 64, bo, bo,
        nullptr, nullptr, (float*)d_out);
}